// round 1
// baseline (speedup 1.0000x reference)
#include <cuda_runtime.h>
#include <math.h>

#define NN 50000
#define NE 200000
#define HID 128

// ---------------- scratch (device globals; no allocation) ----------------
__device__ float g_node_h[(size_t)NN * HID];   // 25.6 MB
__device__ float g_edge_h[(size_t)NE * HID];   // 102.4 MB
__device__ float g_agg[(size_t)NN * HID];      // 25.6 MB
__device__ float g_upd[(size_t)NN * HID];      // 25.6 MB

// ---------------- GEMM: C[M,128] = A[M,K] @ W[K,128] + bias ----------------
// MODE 0: A = arg (stride KTOT), out = g_node_h
// MODE 1: A = arg (stride KTOT), out = g_edge_h
// MODE 2: A = concat(g_node_h, g_agg) (KTOT=256), out = g_upd
template <int KTOT, int MODE>
__global__ void __launch_bounds__(256)
gemm_bias_kernel(const float* __restrict__ A,
                 const float* __restrict__ W,
                 const float* __restrict__ bias,
                 int M)
{
    constexpr int BM = 128, BN = 128, BK = 16;
    __shared__ float As[BK][BM];
    __shared__ float Bs[BK][BN];

    const int tid = threadIdx.x;
    const int tx = tid & 15;        // 0..15 -> cols tx*8..tx*8+7
    const int ty = tid >> 4;        // 0..15 -> rows ty*8..ty*8+7
    const int row0 = blockIdx.x * BM;

    float acc[8][8];
#pragma unroll
    for (int i = 0; i < 8; i++)
#pragma unroll
        for (int j = 0; j < 8; j++) acc[i][j] = 0.f;

    for (int k0 = 0; k0 < KTOT; k0 += BK) {
        // --- load A tile: 128 rows x 16 k (float4 along k), 512 float4 / 256 thr
#pragma unroll
        for (int l = 0; l < 2; l++) {
            int idx = tid + l * 256;
            int r = idx >> 2;             // 0..127
            int kk = (idx & 3) * 4;       // 0,4,8,12
            int grow = row0 + r;
            if (grow >= M) grow = M - 1;  // clamp (results masked at store)
            int k = k0 + kk;
            float4 v;
            if (MODE == 2) {
                const float* src = (k < 128)
                    ? (g_node_h + (size_t)grow * 128 + k)
                    : (g_agg    + (size_t)grow * 128 + (k - 128));
                v = *reinterpret_cast<const float4*>(src);
            } else {
                v = *reinterpret_cast<const float4*>(A + (size_t)grow * KTOT + k);
            }
            As[kk + 0][r] = v.x; As[kk + 1][r] = v.y;
            As[kk + 2][r] = v.z; As[kk + 3][r] = v.w;
        }
        // --- load W tile: 16 x 128
#pragma unroll
        for (int l = 0; l < 2; l++) {
            int idx = tid + l * 256;
            int kk = idx >> 5;            // 0..15
            int n  = (idx & 31) * 4;
            float4 v = *reinterpret_cast<const float4*>(W + (size_t)(k0 + kk) * 128 + n);
            *reinterpret_cast<float4*>(&Bs[kk][n]) = v;
        }
        __syncthreads();

#pragma unroll
        for (int kk = 0; kk < BK; kk++) {
            float a[8], b[8];
#pragma unroll
            for (int i = 0; i < 8; i++) a[i] = As[kk][ty * 8 + i];
#pragma unroll
            for (int j = 0; j < 8; j++) b[j] = Bs[kk][tx * 8 + j];
#pragma unroll
            for (int i = 0; i < 8; i++)
#pragma unroll
                for (int j = 0; j < 8; j++) acc[i][j] += a[i] * b[j];
        }
        __syncthreads();
    }

    float* C = (MODE == 0) ? g_node_h : (MODE == 1) ? g_edge_h : g_upd;
#pragma unroll
    for (int i = 0; i < 8; i++) {
        int grow = row0 + ty * 8 + i;
        if (grow < M) {
#pragma unroll
            for (int j = 0; j < 8; j += 4) {
                int col = tx * 8 + j;
                float4 v;
                v.x = acc[i][j + 0] + bias[col + 0];
                v.y = acc[i][j + 1] + bias[col + 1];
                v.z = acc[i][j + 2] + bias[col + 2];
                v.w = acc[i][j + 3] + bias[col + 3];
                *reinterpret_cast<float4*>(C + (size_t)grow * 128 + col) = v;
            }
        }
    }
}

// ---------------- zero aggregated buffer ----------------
__global__ void zero_agg_kernel()
{
    const int n4 = NN * HID / 4;
    float4 z = make_float4(0.f, 0.f, 0.f, 0.f);
    for (int i = blockIdx.x * blockDim.x + threadIdx.x; i < n4;
         i += gridDim.x * blockDim.x)
        reinterpret_cast<float4*>(g_agg)[i] = z;
}

// ---------------- edge phase: gate + message + scatter-add ----------------
// one warp per edge
__global__ void __launch_bounds__(256)
edge_kernel(const int* __restrict__ src_idx, const int* __restrict__ dst_idx,
            const float* __restrict__ W_top, const float* __restrict__ b_top,
            float* __restrict__ w_out)
{
    int warp = (blockIdx.x * blockDim.x + threadIdx.x) >> 5;
    int lane = threadIdx.x & 31;
    if (warp >= NE) return;

    int s = src_idx[warp];
    int d = dst_idx[warp];

    const float4 sv = *reinterpret_cast<const float4*>(g_node_h + (size_t)s * 128 + lane * 4);
    const float4 dv = *reinterpret_cast<const float4*>(g_node_h + (size_t)d * 128 + lane * 4);
    const float4 ev = *reinterpret_cast<const float4*>(g_edge_h + (size_t)warp * 128 + lane * 4);

    const float4 w0 = *reinterpret_cast<const float4*>(W_top + lane * 4);
    const float4 w1 = *reinterpret_cast<const float4*>(W_top + 128 + lane * 4);
    const float4 w2 = *reinterpret_cast<const float4*>(W_top + 256 + lane * 4);

    float p = sv.x * w0.x + sv.y * w0.y + sv.z * w0.z + sv.w * w0.w
            + dv.x * w1.x + dv.y * w1.y + dv.z * w1.z + dv.w * w1.w
            + ev.x * w2.x + ev.y * w2.y + ev.z * w2.z + ev.w * w2.w;
#pragma unroll
    for (int o = 16; o > 0; o >>= 1) p += __shfl_xor_sync(0xffffffffu, p, o);

    float wgt = 1.f / (1.f + __expf(-(p + b_top[0])));

    float4 msg;
    msg.x = sv.x * wgt + ev.x;
    msg.y = sv.y * wgt + ev.y;
    msg.z = sv.z * wgt + ev.z;
    msg.w = sv.w * wgt + ev.w;

    atomicAdd(reinterpret_cast<float4*>(g_agg + (size_t)d * 128 + lane * 4), msg);

    if (w_out != nullptr && lane == 0) w_out[warp] = wgt;
}

// ---------------- residual + LayerNorm + ReLU ----------------
// one warp per node; TO_OUT: write to d_out instead of g_node_h
template <bool TO_OUT>
__global__ void __launch_bounds__(256)
ln_relu_kernel(const float* __restrict__ scale, const float* __restrict__ bias,
               float* __restrict__ out)
{
    int warp = (blockIdx.x * blockDim.x + threadIdx.x) >> 5;
    int lane = threadIdx.x & 31;
    if (warp >= NN) return;

    size_t base = (size_t)warp * 128 + lane * 4;
    float4 a = *reinterpret_cast<const float4*>(g_node_h + base);
    float4 u = *reinterpret_cast<const float4*>(g_upd + base);
    float4 x;
    x.x = a.x + u.x; x.y = a.y + u.y; x.z = a.z + u.z; x.w = a.w + u.w;

    float s = x.x + x.y + x.z + x.w;
#pragma unroll
    for (int o = 16; o > 0; o >>= 1) s += __shfl_xor_sync(0xffffffffu, s, o);
    float mean = s * (1.f / 128.f);

    float dx = x.x - mean, dy = x.y - mean, dz = x.z - mean, dw = x.w - mean;
    float sq = dx * dx + dy * dy + dz * dz + dw * dw;
#pragma unroll
    for (int o = 16; o > 0; o >>= 1) sq += __shfl_xor_sync(0xffffffffu, sq, o);
    float inv = rsqrtf(sq * (1.f / 128.f) + 1e-6f);

    float4 sc = *reinterpret_cast<const float4*>(scale + lane * 4);
    float4 bi = *reinterpret_cast<const float4*>(bias + lane * 4);

    float4 y;
    y.x = fmaxf(0.f, dx * inv * sc.x + bi.x);
    y.y = fmaxf(0.f, dy * inv * sc.y + bi.y);
    y.z = fmaxf(0.f, dz * inv * sc.z + bi.z);
    y.w = fmaxf(0.f, dw * inv * sc.w + bi.w);

    float* dst = TO_OUT ? out : g_node_h;
    *reinterpret_cast<float4*>(dst + base) = y;
}

// ---------------- launch ----------------
extern "C" void kernel_launch(void* const* d_in, const int* in_sizes, int n_in,
                              void* d_out, int out_size)
{
    const float* nf     = (const float*)d_in[0];
    const float* ef     = (const float*)d_in[1];
    const int*   ei     = (const int*)  d_in[2];
    const float* W_node = (const float*)d_in[3];
    const float* b_node = (const float*)d_in[4];
    const float* W_edge = (const float*)d_in[5];
    const float* b_edge = (const float*)d_in[6];
    const float* W_gnn  = (const float*)d_in[7];   // [3,256,128]
    const float* b_gnn  = (const float*)d_in[8];   // [3,128]
    const float* W_top  = (const float*)d_in[9];   // [384,1]
    const float* b_top  = (const float*)d_in[10];  // [1]
    const float* ln_s   = (const float*)d_in[11];  // [3,128]
    const float* ln_b   = (const float*)d_in[12];  // [3,128]

    float* out        = (float*)d_out;
    float* out_nodes  = out;                       // [NN,128]
    float* out_w      = out + (size_t)NN * 128;    // [NE]

    const int* src = ei;
    const int* dst = ei + NE;

    // embeddings
    gemm_bias_kernel<128, 0><<<(NN + 127) / 128, 256>>>(nf, W_node, b_node, NN);
    gemm_bias_kernel<64,  1><<<(NE + 127) / 128, 256>>>(ef, W_edge, b_edge, NE);

    for (int i = 0; i < 3; i++) {
        zero_agg_kernel<<<2048, 256>>>();
        edge_kernel<<<(NE * 32 + 255) / 256, 256>>>(
            src, dst, W_top, b_top, (i == 2) ? out_w : nullptr);
        gemm_bias_kernel<256, 2><<<(NN + 127) / 128, 256>>>(
            nullptr, W_gnn + (size_t)i * 256 * 128, b_gnn + i * 128, NN);
        if (i == 2)
            ln_relu_kernel<true><<<(NN * 32 + 255) / 256, 256>>>(
                ln_s + i * 128, ln_b + i * 128, out_nodes);
        else
            ln_relu_kernel<false><<<(NN * 32 + 255) / 256, 256>>>(
                ln_s + i * 128, ln_b + i * 128, nullptr);
    }
}

// round 3
// speedup vs baseline: 1.3236x; 1.3236x over previous
#include <cuda_runtime.h>
#include <math.h>
#include <stdint.h>

#define NN 50000
#define NE 200000
#define HID 128

// ---------------- scratch (device globals; no allocation) ----------------
__device__ float g_node_h[(size_t)NN * HID];   // 25.6 MB
__device__ float g_edge_h[(size_t)NE * HID];   // 102.4 MB
__device__ float g_agg[(size_t)NN * HID];      // 25.6 MB
__device__ float g_upd[(size_t)NN * HID];      // 25.6 MB
// transposed weights: WT[n][k] = W[k][n]
__device__ float g_wt_node[128 * 128];
__device__ float g_wt_edge[128 * 64];
__device__ float g_wt_gnn[3 * 128 * 256];

// ---------------- weight transposes into device globals ----------------
__global__ void transpose_node_kernel(const float* __restrict__ W)
{
    int i = blockIdx.x * blockDim.x + threadIdx.x;   // over 128*128
    if (i < 128 * 128) {
        int k = i >> 7, n = i & 127;
        g_wt_node[n * 128 + k] = W[i];
    }
}
__global__ void transpose_edge_kernel(const float* __restrict__ W)
{
    int i = blockIdx.x * blockDim.x + threadIdx.x;   // over 64*128
    if (i < 64 * 128) {
        int k = i >> 7, n = i & 127;
        g_wt_edge[n * 64 + k] = W[i];
    }
}
__global__ void transpose_gnn_kernel(const float* __restrict__ W)
{
    int i = blockIdx.x * blockDim.x + threadIdx.x;   // over 3*256*128
    if (i < 3 * 256 * 128) {
        int l = i / 32768, r = i % 32768;
        int k = r >> 7, n = r & 127;
        g_wt_gnn[l * 32768 + n * 256 + k] = W[i];
    }
}

// ---------------- mma.sync tf32 helpers ----------------
#define MMA_TF32(d, a, b)                                                      \
    asm volatile(                                                              \
        "mma.sync.aligned.m16n8k8.row.col.f32.tf32.tf32.f32 "                  \
        "{%0,%1,%2,%3}, {%4,%5,%6,%7}, {%8,%9}, {%0,%1,%2,%3};"                \
        : "+f"((d)[0]), "+f"((d)[1]), "+f"((d)[2]), "+f"((d)[3])               \
        : "r"(__float_as_uint((a)[0])), "r"(__float_as_uint((a)[1])),          \
          "r"(__float_as_uint((a)[2])), "r"(__float_as_uint((a)[3])),          \
          "r"(__float_as_uint((b)[0])), "r"(__float_as_uint((b)[1])))

__device__ __forceinline__ float tf32_hi(float x) {
    return __uint_as_float(__float_as_uint(x) & 0xFFFFE000u);
}

// ---------------- TF32 split GEMM: C[M,128] = A[M,KTOT] @ W[KTOT,128] + bias
// MODE 0: A = arg, C = g_node_h ; MODE 1: A = arg, C = g_edge_h
// MODE 2: A = concat(g_node_h, g_agg), C = g_upd
template <int KTOT, int MODE>
__global__ void __launch_bounds__(256)
mma_gemm_kernel(const float* __restrict__ A,
                const float* __restrict__ WT,   // [128][KTOT] (B col-major)
                const float* __restrict__ bias,
                int M)
{
    constexpr int NCH = KTOT / 32;
    constexpr int LDS_STRIDE = 36;           // 32 + 4 pad (floats)
    __shared__ float As[128 * LDS_STRIDE];
    __shared__ float Bs[128 * LDS_STRIDE];

    const int tid   = threadIdx.x;
    const int wid   = tid >> 5;
    const int lane  = tid & 31;
    const int warpM = wid >> 1;              // 0..3
    const int warpN = wid & 1;               // 0..1
    const int lq    = lane >> 2;             // 0..7
    const int lr    = lane & 3;              // 0..3
    const int row0  = blockIdx.x * 128;

    float acc[2][8][4];
#pragma unroll
    for (int i = 0; i < 2; i++)
#pragma unroll
        for (int j = 0; j < 8; j++)
#pragma unroll
            for (int q = 0; q < 4; q++) acc[i][j][q] = 0.f;

    float4 sa[4], sb[4];

    // ---- gmem loads for one K-chunk (register staging) ----
    auto load_chunk = [&](int kc) {
#pragma unroll
        for (int l = 0; l < 4; l++) {
            int idx = tid + l * 256;
            int r = idx >> 3;
            int kq = (idx & 7) * 4;
            int grow = row0 + r;
            if (grow >= M) grow = M - 1;
            const float* src;
            if (MODE == 2) {
                int kg = kc * 32 + kq;
                src = (kg < 128) ? g_node_h + (size_t)grow * 128 + kg
                                 : g_agg + (size_t)grow * 128 + (kg - 128);
            } else {
                src = A + (size_t)grow * KTOT + kc * 32 + kq;
            }
            sa[l] = *reinterpret_cast<const float4*>(src);
            sb[l] = *reinterpret_cast<const float4*>(WT + (size_t)r * KTOT + kc * 32 + kq);
        }
    };

    load_chunk(0);

    for (int kc = 0; kc < NCH; kc++) {
        // store staged regs -> smem
#pragma unroll
        for (int l = 0; l < 4; l++) {
            int idx = tid + l * 256;
            int r = idx >> 3;
            int kq = (idx & 7) * 4;
            *reinterpret_cast<float4*>(&As[r * LDS_STRIDE + kq]) = sa[l];
            *reinterpret_cast<float4*>(&Bs[r * LDS_STRIDE + kq]) = sb[l];
        }
        __syncthreads();

        if (kc + 1 < NCH) load_chunk(kc + 1);   // overlap gmem latency with mma

#pragma unroll
        for (int ks = 0; ks < 4; ks++) {
            const int k0 = ks * 8;
            // A fragments (2 m16 tiles), split hi/lo
            float ah[2][4], al[2][4];
#pragma unroll
            for (int tm = 0; tm < 2; tm++) {
                int r = warpM * 32 + tm * 16 + lq;
                float a0 = As[r * LDS_STRIDE + k0 + lr];
                float a1 = As[(r + 8) * LDS_STRIDE + k0 + lr];
                float a2 = As[r * LDS_STRIDE + k0 + 4 + lr];
                float a3 = As[(r + 8) * LDS_STRIDE + k0 + 4 + lr];
                ah[tm][0] = tf32_hi(a0); al[tm][0] = a0 - ah[tm][0];
                ah[tm][1] = tf32_hi(a1); al[tm][1] = a1 - ah[tm][1];
                ah[tm][2] = tf32_hi(a2); al[tm][2] = a2 - ah[tm][2];
                ah[tm][3] = tf32_hi(a3); al[tm][3] = a3 - ah[tm][3];
            }
#pragma unroll
            for (int tn = 0; tn < 8; tn++) {
                int n = warpN * 64 + tn * 8 + lq;
                float b0 = Bs[n * LDS_STRIDE + k0 + lr];
                float b1 = Bs[n * LDS_STRIDE + k0 + 4 + lr];
                float bh[2], bl[2];
                bh[0] = tf32_hi(b0); bl[0] = b0 - bh[0];
                bh[1] = tf32_hi(b1); bl[1] = b1 - bh[1];
                // interleave the 3-term split across the 2 independent accums
                MMA_TF32(acc[0][tn], ah[0], bh);
                MMA_TF32(acc[1][tn], ah[1], bh);
                MMA_TF32(acc[0][tn], al[0], bh);
                MMA_TF32(acc[1][tn], al[1], bh);
                MMA_TF32(acc[0][tn], ah[0], bl);
                MMA_TF32(acc[1][tn], ah[1], bl);
            }
        }
        __syncthreads();
    }

    // ---- epilogue ----
    float* C = (MODE == 0) ? g_node_h : (MODE == 1) ? g_edge_h : g_upd;
#pragma unroll
    for (int tn = 0; tn < 8; tn++) {
        int col = warpN * 64 + tn * 8 + lr * 2;
        float bx = bias[col], by = bias[col + 1];
#pragma unroll
        for (int tm = 0; tm < 2; tm++) {
            int r = row0 + warpM * 32 + tm * 16 + lq;
            if (r < M) {
                float2 v = make_float2(acc[tm][tn][0] + bx, acc[tm][tn][1] + by);
                *reinterpret_cast<float2*>(C + (size_t)r * 128 + col) = v;
            }
            if (r + 8 < M) {
                float2 v = make_float2(acc[tm][tn][2] + bx, acc[tm][tn][3] + by);
                *reinterpret_cast<float2*>(C + (size_t)(r + 8) * 128 + col) = v;
            }
        }
    }
}

// ---------------- zero aggregated buffer ----------------
__global__ void zero_agg_kernel()
{
    const int n4 = NN * HID / 4;
    float4 z = make_float4(0.f, 0.f, 0.f, 0.f);
    for (int i = blockIdx.x * blockDim.x + threadIdx.x; i < n4;
         i += gridDim.x * blockDim.x)
        reinterpret_cast<float4*>(g_agg)[i] = z;
}

// ---------------- edge phase: gate + message + scatter-add ----------------
__global__ void __launch_bounds__(256)
edge_kernel(const int* __restrict__ src_idx, const int* __restrict__ dst_idx,
            const float* __restrict__ W_top, const float* __restrict__ b_top,
            float* __restrict__ w_out)
{
    int warp = (blockIdx.x * blockDim.x + threadIdx.x) >> 5;
    int lane = threadIdx.x & 31;
    if (warp >= NE) return;

    int s = src_idx[warp];
    int d = dst_idx[warp];

    const float4 sv = *reinterpret_cast<const float4*>(g_node_h + (size_t)s * 128 + lane * 4);
    const float4 dv = *reinterpret_cast<const float4*>(g_node_h + (size_t)d * 128 + lane * 4);
    const float4 ev = *reinterpret_cast<const float4*>(g_edge_h + (size_t)warp * 128 + lane * 4);

    const float4 w0 = *reinterpret_cast<const float4*>(W_top + lane * 4);
    const float4 w1 = *reinterpret_cast<const float4*>(W_top + 128 + lane * 4);
    const float4 w2 = *reinterpret_cast<const float4*>(W_top + 256 + lane * 4);

    float p = sv.x * w0.x + sv.y * w0.y + sv.z * w0.z + sv.w * w0.w
            + dv.x * w1.x + dv.y * w1.y + dv.z * w1.z + dv.w * w1.w
            + ev.x * w2.x + ev.y * w2.y + ev.z * w2.z + ev.w * w2.w;
#pragma unroll
    for (int o = 16; o > 0; o >>= 1) p += __shfl_xor_sync(0xffffffffu, p, o);

    float wgt = 1.f / (1.f + __expf(-(p + b_top[0])));

    float4 msg;
    msg.x = sv.x * wgt + ev.x;
    msg.y = sv.y * wgt + ev.y;
    msg.z = sv.z * wgt + ev.z;
    msg.w = sv.w * wgt + ev.w;

    atomicAdd(reinterpret_cast<float4*>(g_agg + (size_t)d * 128 + lane * 4), msg);

    if (w_out != nullptr && lane == 0) w_out[warp] = wgt;
}

// ---------------- residual + LayerNorm + ReLU ----------------
template <bool TO_OUT>
__global__ void __launch_bounds__(256)
ln_relu_kernel(const float* __restrict__ scale, const float* __restrict__ bias,
               float* __restrict__ out)
{
    int warp = (blockIdx.x * blockDim.x + threadIdx.x) >> 5;
    int lane = threadIdx.x & 31;
    if (warp >= NN) return;

    size_t base = (size_t)warp * 128 + lane * 4;
    float4 a = *reinterpret_cast<const float4*>(g_node_h + base);
    float4 u = *reinterpret_cast<const float4*>(g_upd + base);
    float4 x;
    x.x = a.x + u.x; x.y = a.y + u.y; x.z = a.z + u.z; x.w = a.w + u.w;

    float s = x.x + x.y + x.z + x.w;
#pragma unroll
    for (int o = 16; o > 0; o >>= 1) s += __shfl_xor_sync(0xffffffffu, s, o);
    float mean = s * (1.f / 128.f);

    float dx = x.x - mean, dy = x.y - mean, dz = x.z - mean, dw = x.w - mean;
    float sq = dx * dx + dy * dy + dz * dz + dw * dw;
#pragma unroll
    for (int o = 16; o > 0; o >>= 1) sq += __shfl_xor_sync(0xffffffffu, sq, o);
    float inv = rsqrtf(sq * (1.f / 128.f) + 1e-6f);

    float4 sc = *reinterpret_cast<const float4*>(scale + lane * 4);
    float4 bi = *reinterpret_cast<const float4*>(bias + lane * 4);

    float4 y;
    y.x = fmaxf(0.f, dx * inv * sc.x + bi.x);
    y.y = fmaxf(0.f, dy * inv * sc.y + bi.y);
    y.z = fmaxf(0.f, dz * inv * sc.z + bi.z);
    y.w = fmaxf(0.f, dw * inv * sc.w + bi.w);

    float* dst = TO_OUT ? out : g_node_h;
    *reinterpret_cast<float4*>(dst + base) = y;
}

// ---------------- launch ----------------
extern "C" void kernel_launch(void* const* d_in, const int* in_sizes, int n_in,
                              void* d_out, int out_size)
{
    const float* nf     = (const float*)d_in[0];
    const float* ef     = (const float*)d_in[1];
    const int*   ei     = (const int*)  d_in[2];
    const float* W_node = (const float*)d_in[3];
    const float* b_node = (const float*)d_in[4];
    const float* W_edge = (const float*)d_in[5];
    const float* b_edge = (const float*)d_in[6];
    const float* W_gnn  = (const float*)d_in[7];   // [3,256,128]
    const float* b_gnn  = (const float*)d_in[8];   // [3,128]
    const float* W_top  = (const float*)d_in[9];   // [384,1]
    const float* b_top  = (const float*)d_in[10];  // [1]
    const float* ln_s   = (const float*)d_in[11];  // [3,128]
    const float* ln_b   = (const float*)d_in[12];  // [3,128]

    float* out        = (float*)d_out;
    float* out_nodes  = out;                       // [NN,128]
    float* out_w      = out + (size_t)NN * 128;    // [NE]

    const int* src = ei;
    const int* dst = ei + NE;

    static float* wtn = nullptr;
    static float* wte = nullptr;
    static float* wtg = nullptr;
    if (wtn == nullptr) {
        cudaGetSymbolAddress((void**)&wtn, g_wt_node);
        cudaGetSymbolAddress((void**)&wte, g_wt_edge);
        cudaGetSymbolAddress((void**)&wtg, g_wt_gnn);
    }

    // weight transposes (WT written to device globals)
    transpose_node_kernel<<<(128 * 128 + 255) / 256, 256>>>(W_node);
    transpose_edge_kernel<<<(64 * 128 + 255) / 256, 256>>>(W_edge);
    transpose_gnn_kernel<<<(3 * 256 * 128 + 255) / 256, 256>>>(W_gnn);

    // embeddings
    mma_gemm_kernel<128, 0><<<(NN + 127) / 128, 256>>>(nf, wtn, b_node, NN);
    mma_gemm_kernel<64, 1><<<(NE + 127) / 128, 256>>>(ef, wte, b_edge, NE);

    for (int i = 0; i < 3; i++) {
        zero_agg_kernel<<<2048, 256>>>();
        edge_kernel<<<(NE * 32 + 255) / 256, 256>>>(
            src, dst, W_top, b_top, (i == 2) ? out_w : nullptr);
        mma_gemm_kernel<256, 2><<<(NN + 127) / 128, 256>>>(
            nullptr, wtg + (size_t)i * 128 * 256, b_gnn + i * 128, NN);
        if (i == 2)
            ln_relu_kernel<true><<<(NN * 32 + 255) / 256, 256>>>(
                ln_s + i * 128, ln_b + i * 128, out_nodes);
        else
            ln_relu_kernel<false><<<(NN * 32 + 255) / 256, 256>>>(
                ln_s + i * 128, ln_b + i * 128, nullptr);
    }
}

// round 4
// speedup vs baseline: 1.3636x; 1.0302x over previous
#include <cuda_runtime.h>
#include <math.h>
#include <stdint.h>

#define NN 50000
#define NE 200000

// ---------------- scratch (device globals; no allocation) ----------------
__device__ float g_node_h[(size_t)NN * 128];
__device__ float g_agg[(size_t)NN * 128];
__device__ float g_agg_e[(size_t)NN * 128];   // layer-invariant: sum of edge_h into dst
__device__ float g_a[NN];                     // node_h . w0
__device__ float g_b[NN];                     // node_h . w1
__device__ float g_edot[NE];                  // edge_h . w2 (layer-invariant)
__device__ float g_wt_node[128 * 128];
__device__ float g_wt_edge[128 * 64];
__device__ float g_wt_gnn[3 * 128 * 256];

// ---------------- weight transposes ----------------
__global__ void transpose_node_kernel(const float* __restrict__ W)
{
    int i = blockIdx.x * blockDim.x + threadIdx.x;
    if (i < 128 * 128) { int k = i >> 7, n = i & 127; g_wt_node[n * 128 + k] = W[i]; }
}
__global__ void transpose_edge_kernel(const float* __restrict__ W)
{
    int i = blockIdx.x * blockDim.x + threadIdx.x;
    if (i < 64 * 128) { int k = i >> 7, n = i & 127; g_wt_edge[n * 64 + k] = W[i]; }
}
__global__ void transpose_gnn_kernel(const float* __restrict__ W)
{
    int i = blockIdx.x * blockDim.x + threadIdx.x;
    if (i < 3 * 256 * 128) {
        int l = i / 32768, r = i % 32768;
        int k = r >> 7, n = r & 127;
        g_wt_gnn[l * 32768 + n * 256 + k] = W[i];
    }
}

// ---------------- zero / copy helpers ----------------
__global__ void zero_agg_e_kernel()
{
    const int n4 = NN * 128 / 4;
    float4 z = make_float4(0.f, 0.f, 0.f, 0.f);
    for (int i = blockIdx.x * blockDim.x + threadIdx.x; i < n4; i += gridDim.x * blockDim.x)
        reinterpret_cast<float4*>(g_agg_e)[i] = z;
}
__global__ void copy_agg_kernel()   // g_agg = g_agg_e
{
    const int n4 = NN * 128 / 4;
    for (int i = blockIdx.x * blockDim.x + threadIdx.x; i < n4; i += gridDim.x * blockDim.x)
        reinterpret_cast<float4*>(g_agg)[i] = reinterpret_cast<const float4*>(g_agg_e)[i];
}

// ---------------- mma / cp.async helpers ----------------
#define MMA_TF32(d, a, b)                                                      \
    asm volatile(                                                              \
        "mma.sync.aligned.m16n8k8.row.col.f32.tf32.tf32.f32 "                  \
        "{%0,%1,%2,%3}, {%4,%5,%6,%7}, {%8,%9}, {%0,%1,%2,%3};"                \
        : "+f"((d)[0]), "+f"((d)[1]), "+f"((d)[2]), "+f"((d)[3])               \
        : "r"(__float_as_uint((a)[0])), "r"(__float_as_uint((a)[1])),          \
          "r"(__float_as_uint((a)[2])), "r"(__float_as_uint((a)[3])),          \
          "r"(__float_as_uint((b)[0])), "r"(__float_as_uint((b)[1])))

#define CP_ASYNC16(saddr, gptr) \
    asm volatile("cp.async.cg.shared.global [%0], [%1], 16;" :: "r"(saddr), "l"(gptr))
#define CP_COMMIT() asm volatile("cp.async.commit_group;")
#define CP_WAIT0()  asm volatile("cp.async.wait_group 0;")

__device__ __forceinline__ float tf32_hi(float x) {
    return __uint_as_float(__float_as_uint(x) & 0xFFFFE000u);
}

// =====================================================================
// Fused TF32-split GEMM. C[M,128] = A[M,KTOT] @ W + bias, plus fused epilogues:
// MODE 0 (node embed):  write g_node_h; compute a = y.w0, b = y.w1
// MODE 1 (edge embed):  NO C write; edot[e] = y.w2; atomicAdd rows into g_agg_e[dst]
// MODE 2 (update):      x = node_h + (acc+bias); LayerNorm+ReLU -> dest;
//                       if doab: a,b dots of result
// =====================================================================
template <int KTOT, int MODE>
__global__ void __launch_bounds__(256)
mma_gemm_kernel(const float* __restrict__ A,
                const float* __restrict__ WT,
                const float* __restrict__ bias,
                int M,
                const float* __restrict__ aux,    // MODE0: W_top; MODE1: W_top+256; MODE2: W_top
                const int* __restrict__ dst_idx,  // MODE1
                const float* __restrict__ lns,    // MODE2
                const float* __restrict__ lnb,    // MODE2
                float* __restrict__ dest,         // MODE2 output (g_node_h or d_out)
                int doab)
{
    extern __shared__ float smem[];
    constexpr int NCH = KTOT / 32;
    constexpr int STRIDE = 36;                // floats, 32+4 pad
    constexpr int TILE = 128 * STRIDE;        // 4608 floats per tile
    // layout: [A0][B0][A1][B1]

    const int tid   = threadIdx.x;
    const int wid   = tid >> 5;
    const int lane  = tid & 31;
    const int warpM = wid >> 1;
    const int warpN = wid & 1;
    const int lq    = lane >> 2;
    const int lr    = lane & 3;
    const int row0  = blockIdx.x * 128;

    const uint32_t sbase = (uint32_t)__cvta_generic_to_shared(smem);

    float acc[2][8][4];
#pragma unroll
    for (int i = 0; i < 2; i++)
#pragma unroll
        for (int j = 0; j < 8; j++)
#pragma unroll
            for (int q = 0; q < 4; q++) acc[i][j][q] = 0.f;

    auto issue_chunk = [&](int kc, int buf) {
        const int kbase = kc * 32;
#pragma unroll
        for (int l = 0; l < 4; l++) {
            int idx = tid + l * 256;
            int r = idx >> 3;
            int kq = (idx & 7) * 4;
            int grow = row0 + r;
            if (grow >= M) grow = M - 1;
            const float* srcA;
            if (MODE == 2) {
                int kg = kbase + kq;
                srcA = (kg < 128) ? g_node_h + (size_t)grow * 128 + kg
                                  : g_agg + (size_t)grow * 128 + (kg - 128);
            } else {
                srcA = A + (size_t)grow * KTOT + kbase + kq;
            }
            uint32_t sa = sbase + (uint32_t)((buf * 2 * TILE + r * STRIDE + kq) * 4);
            CP_ASYNC16(sa, srcA);
            const float* srcB = WT + (size_t)r * KTOT + kbase + kq;
            uint32_t sb = sbase + (uint32_t)((buf * 2 * TILE + TILE + r * STRIDE + kq) * 4);
            CP_ASYNC16(sb, srcB);
        }
        CP_COMMIT();
    };

    issue_chunk(0, 0);

    for (int kc = 0; kc < NCH; kc++) {
        const int cur = kc & 1;
        CP_WAIT0();
        __syncthreads();
        if (kc + 1 < NCH) issue_chunk(kc + 1, cur ^ 1);

        const float* As = smem + cur * 2 * TILE;
        const float* Bs = As + TILE;

#pragma unroll
        for (int ks = 0; ks < 4; ks++) {
            const int k0 = ks * 8;
            float ah[2][4], al[2][4];
#pragma unroll
            for (int tm = 0; tm < 2; tm++) {
                int r = warpM * 32 + tm * 16 + lq;
                float a0 = As[r * STRIDE + k0 + lr];
                float a1 = As[(r + 8) * STRIDE + k0 + lr];
                float a2 = As[r * STRIDE + k0 + 4 + lr];
                float a3 = As[(r + 8) * STRIDE + k0 + 4 + lr];
                ah[tm][0] = tf32_hi(a0); al[tm][0] = a0 - ah[tm][0];
                ah[tm][1] = tf32_hi(a1); al[tm][1] = a1 - ah[tm][1];
                ah[tm][2] = tf32_hi(a2); al[tm][2] = a2 - ah[tm][2];
                ah[tm][3] = tf32_hi(a3); al[tm][3] = a3 - ah[tm][3];
            }
#pragma unroll
            for (int tn = 0; tn < 8; tn++) {
                int n = warpN * 64 + tn * 8 + lq;
                float b0 = Bs[n * STRIDE + k0 + lr];
                float b1 = Bs[n * STRIDE + k0 + 4 + lr];
                float bh[2], bl[2];
                bh[0] = tf32_hi(b0); bl[0] = b0 - bh[0];
                bh[1] = tf32_hi(b1); bl[1] = b1 - bh[1];
                MMA_TF32(acc[0][tn], ah[0], bh);
                MMA_TF32(acc[1][tn], ah[1], bh);
                MMA_TF32(acc[0][tn], al[0], bh);
                MMA_TF32(acc[1][tn], al[1], bh);
                MMA_TF32(acc[0][tn], ah[0], bl);
                MMA_TF32(acc[1][tn], ah[1], bl);
            }
        }
        __syncthreads();
    }

    // ---------------- epilogue ----------------
    // add bias into acc
#pragma unroll
    for (int tn = 0; tn < 8; tn++) {
        int col = warpN * 64 + tn * 8 + lr * 2;
        float bx = bias[col], by = bias[col + 1];
#pragma unroll
        for (int tm = 0; tm < 2; tm++) {
            acc[tm][tn][0] += bx; acc[tm][tn][1] += by;
            acc[tm][tn][2] += bx; acc[tm][tn][3] += by;
        }
    }
    // row indices owned by this thread
    int rl[2][2], rg[2][2];
#pragma unroll
    for (int tm = 0; tm < 2; tm++) {
        rl[tm][0] = warpM * 32 + tm * 16 + lq;
        rl[tm][1] = rl[tm][0] + 8;
        rg[tm][0] = row0 + rl[tm][0];
        rg[tm][1] = row0 + rl[tm][1];
    }

    float* red0 = smem;          // [128]
    float* red1 = smem + 128;    // [128]

    if (MODE == 0) {
        // write C and compute a,b dots on y
        float pa[2][2] = {{0,0},{0,0}}, pb[2][2] = {{0,0},{0,0}};
#pragma unroll
        for (int tn = 0; tn < 8; tn++) {
            int col = warpN * 64 + tn * 8 + lr * 2;
            float w0x = aux[col], w0y = aux[col + 1];
            float w1x = aux[128 + col], w1y = aux[128 + col + 1];
#pragma unroll
            for (int tm = 0; tm < 2; tm++) {
#pragma unroll
                for (int h = 0; h < 2; h++) {
                    float vx = acc[tm][tn][h * 2], vy = acc[tm][tn][h * 2 + 1];
                    if (rg[tm][h] < M)
                        *reinterpret_cast<float2*>(g_node_h + (size_t)rg[tm][h] * 128 + col)
                            = make_float2(vx, vy);
                    pa[tm][h] += vx * w0x + vy * w0y;
                    pb[tm][h] += vx * w1x + vy * w1y;
                }
            }
        }
        if (tid < 128) { red0[tid] = 0.f; red1[tid] = 0.f; }
        __syncthreads();
#pragma unroll
        for (int tm = 0; tm < 2; tm++)
#pragma unroll
            for (int h = 0; h < 2; h++) {
#pragma unroll
                for (int o = 1; o <= 2; o <<= 1) {
                    pa[tm][h] += __shfl_xor_sync(0xffffffffu, pa[tm][h], o);
                    pb[tm][h] += __shfl_xor_sync(0xffffffffu, pb[tm][h], o);
                }
                if (lr == 0) {
                    atomicAdd(&red0[rl[tm][h]], pa[tm][h]);
                    atomicAdd(&red1[rl[tm][h]], pb[tm][h]);
                }
            }
        __syncthreads();
        if (tid < 128 && row0 + tid < M) {
            g_a[row0 + tid] = red0[tid];
            g_b[row0 + tid] = red1[tid];
        }
    }
    else if (MODE == 1) {
        // edot + scatter rows into g_agg_e[dst]
        int dsts[2][2];
#pragma unroll
        for (int tm = 0; tm < 2; tm++)
#pragma unroll
            for (int h = 0; h < 2; h++)
                dsts[tm][h] = (rg[tm][h] < M) ? dst_idx[rg[tm][h]] : -1;

        float pd[2][2] = {{0,0},{0,0}};
#pragma unroll
        for (int tn = 0; tn < 8; tn++) {
            int col = warpN * 64 + tn * 8 + lr * 2;
            float w2x = aux[col], w2y = aux[col + 1];
#pragma unroll
            for (int tm = 0; tm < 2; tm++) {
#pragma unroll
                for (int h = 0; h < 2; h++) {
                    float vx = acc[tm][tn][h * 2], vy = acc[tm][tn][h * 2 + 1];
                    pd[tm][h] += vx * w2x + vy * w2y;
                    if (dsts[tm][h] >= 0)
                        atomicAdd(reinterpret_cast<float2*>(
                            g_agg_e + (size_t)dsts[tm][h] * 128 + col),
                            make_float2(vx, vy));
                }
            }
        }
        if (tid < 128) red0[tid] = 0.f;
        __syncthreads();
#pragma unroll
        for (int tm = 0; tm < 2; tm++)
#pragma unroll
            for (int h = 0; h < 2; h++) {
#pragma unroll
                for (int o = 1; o <= 2; o <<= 1)
                    pd[tm][h] += __shfl_xor_sync(0xffffffffu, pd[tm][h], o);
                if (lr == 0) atomicAdd(&red0[rl[tm][h]], pd[tm][h]);
            }
        __syncthreads();
        if (tid < 128 && row0 + tid < M)
            g_edot[row0 + tid] = red0[tid];
    }
    else {
        // MODE 2: residual + LayerNorm + ReLU (+ optional a,b dots)
        float ps[2][2] = {{0,0},{0,0}}, pq[2][2] = {{0,0},{0,0}};
#pragma unroll
        for (int tn = 0; tn < 8; tn++) {
            int col = warpN * 64 + tn * 8 + lr * 2;
#pragma unroll
            for (int tm = 0; tm < 2; tm++) {
#pragma unroll
                for (int h = 0; h < 2; h++) {
                    float2 res = (rg[tm][h] < M)
                        ? *reinterpret_cast<const float2*>(g_node_h + (size_t)rg[tm][h] * 128 + col)
                        : make_float2(0.f, 0.f);
                    float x0 = acc[tm][tn][h * 2] + res.x;
                    float x1 = acc[tm][tn][h * 2 + 1] + res.y;
                    acc[tm][tn][h * 2] = x0;
                    acc[tm][tn][h * 2 + 1] = x1;
                    ps[tm][h] += x0 + x1;
                    pq[tm][h] += x0 * x0 + x1 * x1;
                }
            }
        }
        if (tid < 128) { red0[tid] = 0.f; red1[tid] = 0.f; }
        __syncthreads();
#pragma unroll
        for (int tm = 0; tm < 2; tm++)
#pragma unroll
            for (int h = 0; h < 2; h++) {
#pragma unroll
                for (int o = 1; o <= 2; o <<= 1) {
                    ps[tm][h] += __shfl_xor_sync(0xffffffffu, ps[tm][h], o);
                    pq[tm][h] += __shfl_xor_sync(0xffffffffu, pq[tm][h], o);
                }
                if (lr == 0) {
                    atomicAdd(&red0[rl[tm][h]], ps[tm][h]);
                    atomicAdd(&red1[rl[tm][h]], pq[tm][h]);
                }
            }
        __syncthreads();
        float mean_[2][2], inv_[2][2];
#pragma unroll
        for (int tm = 0; tm < 2; tm++)
#pragma unroll
            for (int h = 0; h < 2; h++) {
                float m = red0[rl[tm][h]] * (1.f / 128.f);
                float var = red1[rl[tm][h]] * (1.f / 128.f) - m * m;
                mean_[tm][h] = m;
                inv_[tm][h] = rsqrtf(fmaxf(var, 0.f) + 1e-6f);
            }
        float pa[2][2] = {{0,0},{0,0}}, pb[2][2] = {{0,0},{0,0}};
#pragma unroll
        for (int tn = 0; tn < 8; tn++) {
            int col = warpN * 64 + tn * 8 + lr * 2;
            float scx = lns[col], scy = lns[col + 1];
            float bix = lnb[col], biy = lnb[col + 1];
            float w0x = aux[col], w0y = aux[col + 1];
            float w1x = aux[128 + col], w1y = aux[128 + col + 1];
#pragma unroll
            for (int tm = 0; tm < 2; tm++) {
#pragma unroll
                for (int h = 0; h < 2; h++) {
                    float y0 = fmaxf(0.f, (acc[tm][tn][h * 2] - mean_[tm][h]) * inv_[tm][h] * scx + bix);
                    float y1 = fmaxf(0.f, (acc[tm][tn][h * 2 + 1] - mean_[tm][h]) * inv_[tm][h] * scy + biy);
                    if (rg[tm][h] < M)
                        *reinterpret_cast<float2*>(dest + (size_t)rg[tm][h] * 128 + col)
                            = make_float2(y0, y1);
                    pa[tm][h] += y0 * w0x + y1 * w0y;
                    pb[tm][h] += y0 * w1x + y1 * w1y;
                }
            }
        }
        if (doab) {
            __syncthreads();
            if (tid < 128) { red0[tid] = 0.f; red1[tid] = 0.f; }
            __syncthreads();
#pragma unroll
            for (int tm = 0; tm < 2; tm++)
#pragma unroll
                for (int h = 0; h < 2; h++) {
#pragma unroll
                    for (int o = 1; o <= 2; o <<= 1) {
                        pa[tm][h] += __shfl_xor_sync(0xffffffffu, pa[tm][h], o);
                        pb[tm][h] += __shfl_xor_sync(0xffffffffu, pb[tm][h], o);
                    }
                    if (lr == 0) {
                        atomicAdd(&red0[rl[tm][h]], pa[tm][h]);
                        atomicAdd(&red1[rl[tm][h]], pb[tm][h]);
                    }
                }
            __syncthreads();
            if (tid < 128 && row0 + tid < M) {
                g_a[row0 + tid] = red0[tid];
                g_b[row0 + tid] = red1[tid];
            }
        }
    }
}

// ---------------- per-layer edge phase: gate + scatter src_f*wgt ----------------
__global__ void __launch_bounds__(256)
edge_kernel(const int* __restrict__ src_idx, const int* __restrict__ dst_idx,
            const float* __restrict__ b_top, float* __restrict__ w_out)
{
    int e = (blockIdx.x * blockDim.x + threadIdx.x) >> 5;
    int lane = threadIdx.x & 31;
    if (e >= NE) return;

    int s = src_idx[e];
    int d = dst_idx[e];

    float wgt;
    if (lane == 0) {
        float g = g_a[s] + g_b[d] + g_edot[e] + b_top[0];
        wgt = 1.f / (1.f + __expf(-g));
    }
    wgt = __shfl_sync(0xffffffffu, wgt, 0);

    float4 sv = *reinterpret_cast<const float4*>(g_node_h + (size_t)s * 128 + lane * 4);
    float4 msg = make_float4(sv.x * wgt, sv.y * wgt, sv.z * wgt, sv.w * wgt);
    atomicAdd(reinterpret_cast<float4*>(g_agg + (size_t)d * 128 + lane * 4), msg);

    if (w_out != nullptr && lane == 0) w_out[e] = wgt;
}

// ---------------- launch ----------------
extern "C" void kernel_launch(void* const* d_in, const int* in_sizes, int n_in,
                              void* d_out, int out_size)
{
    const float* nf     = (const float*)d_in[0];
    const float* ef     = (const float*)d_in[1];
    const int*   ei     = (const int*)  d_in[2];
    const float* W_node = (const float*)d_in[3];
    const float* b_node = (const float*)d_in[4];
    const float* W_edge = (const float*)d_in[5];
    const float* b_edge = (const float*)d_in[6];
    const float* W_gnn  = (const float*)d_in[7];
    const float* b_gnn  = (const float*)d_in[8];
    const float* W_top  = (const float*)d_in[9];
    const float* b_top  = (const float*)d_in[10];
    const float* ln_s   = (const float*)d_in[11];
    const float* ln_b   = (const float*)d_in[12];

    float* out       = (float*)d_out;
    float* out_nodes = out;
    float* out_w     = out + (size_t)NN * 128;

    const int* src = ei;
    const int* dst = ei + NE;

    const int SMEM_SZ = 4 * 128 * 36 * 4;   // 73728 B
    cudaFuncSetAttribute(mma_gemm_kernel<128, 0>, cudaFuncAttributeMaxDynamicSharedMemorySize, SMEM_SZ);
    cudaFuncSetAttribute(mma_gemm_kernel<64, 1>,  cudaFuncAttributeMaxDynamicSharedMemorySize, SMEM_SZ);
    cudaFuncSetAttribute(mma_gemm_kernel<256, 2>, cudaFuncAttributeMaxDynamicSharedMemorySize, SMEM_SZ);

    float* wtn = nullptr; float* wte = nullptr; float* wtg = nullptr;
    cudaGetSymbolAddress((void**)&wtn, g_wt_node);
    cudaGetSymbolAddress((void**)&wte, g_wt_edge);
    cudaGetSymbolAddress((void**)&wtg, g_wt_gnn);
    float* nodeh = nullptr;
    cudaGetSymbolAddress((void**)&nodeh, g_node_h);

    zero_agg_e_kernel<<<2048, 256>>>();
    transpose_node_kernel<<<(128 * 128 + 255) / 256, 256>>>(W_node);
    transpose_edge_kernel<<<(64 * 128 + 255) / 256, 256>>>(W_edge);
    transpose_gnn_kernel<<<(3 * 256 * 128 + 255) / 256, 256>>>(W_gnn);

    // node embed (+ a,b dots)
    mma_gemm_kernel<128, 0><<<(NN + 127) / 128, 256, SMEM_SZ>>>(
        nf, wtn, b_node, NN, W_top, nullptr, nullptr, nullptr, nullptr, 0);
    // edge embed (edot + agg_e; edge_h never materialized)
    mma_gemm_kernel<64, 1><<<(NE + 127) / 128, 256, SMEM_SZ>>>(
        ef, wte, b_edge, NE, W_top + 256, dst, nullptr, nullptr, nullptr, 0);

    for (int i = 0; i < 3; i++) {
        copy_agg_kernel<<<2048, 256>>>();
        edge_kernel<<<(NE * 32 + 255) / 256, 256>>>(
            src, dst, b_top, (i == 2) ? out_w : nullptr);
        mma_gemm_kernel<256, 2><<<(NN + 127) / 128, 256, SMEM_SZ>>>(
            nullptr, wtg + (size_t)i * 128 * 256, b_gnn + i * 128, NN,
            W_top, nullptr, ln_s + i * 128, ln_b + i * 128,
            (i == 2) ? out_nodes : nodeh, (i < 2) ? 1 : 0);
    }
}

// round 5
// speedup vs baseline: 1.6845x; 1.2353x over previous
#include <cuda_runtime.h>
#include <math.h>
#include <stdint.h>

#define NN 50000
#define NE 200000

// ---------------- scratch (device globals; no allocation) ----------------
__device__ float g_node_h[(size_t)NN * 128];
__device__ float g_agg[(size_t)NN * 128];
__device__ float g_agg_e[(size_t)NN * 128];   // layer-invariant: sum of edge_h into dst
__device__ float g_a[NN];                     // node_h . w0
__device__ float g_b[NN];                     // node_h . w1
__device__ float g_edot[NE];                  // edge_h . w2 (layer-invariant)
__device__ float g_wt_node[128 * 128];
__device__ float g_wt_edge[128 * 64];
__device__ float g_wt_gnn[3 * 128 * 256];

// ---------------- weight transposes ----------------
__global__ void transpose_node_kernel(const float* __restrict__ W)
{
    int i = blockIdx.x * blockDim.x + threadIdx.x;
    if (i < 128 * 128) { int k = i >> 7, n = i & 127; g_wt_node[n * 128 + k] = W[i]; }
}
__global__ void transpose_edge_kernel(const float* __restrict__ W)
{
    int i = blockIdx.x * blockDim.x + threadIdx.x;
    if (i < 64 * 128) { int k = i >> 7, n = i & 127; g_wt_edge[n * 64 + k] = W[i]; }
}
__global__ void transpose_gnn_kernel(const float* __restrict__ W)
{
    int i = blockIdx.x * blockDim.x + threadIdx.x;
    if (i < 3 * 256 * 128) {
        int l = i / 32768, r = i % 32768;
        int k = r >> 7, n = r & 127;
        g_wt_gnn[l * 32768 + n * 256 + k] = W[i];
    }
}

// ---------------- zero / copy helpers ----------------
__global__ void zero_agg_e_kernel()
{
    const int n4 = NN * 128 / 4;
    float4 z = make_float4(0.f, 0.f, 0.f, 0.f);
    for (int i = blockIdx.x * blockDim.x + threadIdx.x; i < n4; i += gridDim.x * blockDim.x)
        reinterpret_cast<float4*>(g_agg_e)[i] = z;
}
__global__ void copy_agg_kernel()   // g_agg = g_agg_e
{
    const int n4 = NN * 128 / 4;
    for (int i = blockIdx.x * blockDim.x + threadIdx.x; i < n4; i += gridDim.x * blockDim.x)
        reinterpret_cast<float4*>(g_agg)[i] = reinterpret_cast<const float4*>(g_agg_e)[i];
}

// ---------------- mma / cp.async / bf16 helpers ----------------
#define MMA_BF16(d, a0, a1, a2, a3, b0, b1)                                    \
    asm volatile(                                                              \
        "mma.sync.aligned.m16n8k16.row.col.f32.bf16.bf16.f32 "                 \
        "{%0,%1,%2,%3}, {%4,%5,%6,%7}, {%8,%9}, {%0,%1,%2,%3};"                \
        : "+f"((d)[0]), "+f"((d)[1]), "+f"((d)[2]), "+f"((d)[3])               \
        : "r"(a0), "r"(a1), "r"(a2), "r"(a3), "r"(b0), "r"(b1))

#define CP_ASYNC16(saddr, gptr) \
    asm volatile("cp.async.cg.shared.global [%0], [%1], 16;" :: "r"(saddr), "l"(gptr))
#define CP_COMMIT() asm volatile("cp.async.commit_group;")
#define CP_WAIT0()  asm volatile("cp.async.wait_group 0;")

// pack (f.x -> low, f.y -> high) bf16x2 and return fp32 remainder
__device__ __forceinline__ uint32_t bf16x2_split(float2 f, float2& rem) {
    uint32_t h;
    asm("cvt.rn.bf16x2.f32 %0, %1, %2;" : "=r"(h) : "f"(f.y), "f"(f.x));
    float hx = __uint_as_float(h << 16);
    float hy = __uint_as_float(h & 0xFFFF0000u);
    rem.x = f.x - hx;
    rem.y = f.y - hy;
    return h;
}
__device__ __forceinline__ uint32_t bf16x2_pack(float2 f) {
    uint32_t h;
    asm("cvt.rn.bf16x2.f32 %0, %1, %2;" : "=r"(h) : "f"(f.y), "f"(f.x));
    return h;
}

// =====================================================================
// Fused bf16x2-split GEMM. C[M,128] = A[M,KTOT] @ W + bias, fused epilogues:
// MODE 0 (node embed):  write g_node_h; a = y.w0, b = y.w1
// MODE 1 (edge embed):  NO C write; edot[e] = y.w2; atomicAdd rows into g_agg_e[dst]
// MODE 2 (update):      x = node_h + (acc+bias); LayerNorm+ReLU -> dest; opt a,b dots
// =====================================================================
template <int KTOT, int MODE>
__global__ void __launch_bounds__(256, 2)
mma_gemm_kernel(const float* __restrict__ A,
                const float* __restrict__ WT,
                const float* __restrict__ bias,
                int M,
                const float* __restrict__ aux,
                const int* __restrict__ dst_idx,
                const float* __restrict__ lns,
                const float* __restrict__ lnb,
                float* __restrict__ dest,
                int doab)
{
    extern __shared__ float smem[];
    constexpr int NCH = KTOT / 32;
    constexpr int STRIDE = 36;                // floats, 32+4 pad
    constexpr int TILE = 128 * STRIDE;

    const int tid   = threadIdx.x;
    const int wid   = tid >> 5;
    const int lane  = tid & 31;
    const int warpM = wid >> 1;
    const int warpN = wid & 1;
    const int lq    = lane >> 2;
    const int lr    = lane & 3;
    const int row0  = blockIdx.x * 128;

    const uint32_t sbase = (uint32_t)__cvta_generic_to_shared(smem);

    float acc[2][8][4];
#pragma unroll
    for (int i = 0; i < 2; i++)
#pragma unroll
        for (int j = 0; j < 8; j++)
#pragma unroll
            for (int q = 0; q < 4; q++) acc[i][j][q] = 0.f;

    auto issue_chunk = [&](int kc, int buf) {
        const int kbase = kc * 32;
#pragma unroll
        for (int l = 0; l < 4; l++) {
            int idx = tid + l * 256;
            int r = idx >> 3;
            int kq = (idx & 7) * 4;
            int grow = row0 + r;
            if (grow >= M) grow = M - 1;
            const float* srcA;
            if (MODE == 2) {
                int kg = kbase + kq;
                srcA = (kg < 128) ? g_node_h + (size_t)grow * 128 + kg
                                  : g_agg + (size_t)grow * 128 + (kg - 128);
            } else {
                srcA = A + (size_t)grow * KTOT + kbase + kq;
            }
            uint32_t sa = sbase + (uint32_t)((buf * 2 * TILE + r * STRIDE + kq) * 4);
            CP_ASYNC16(sa, srcA);
            const float* srcB = WT + (size_t)r * KTOT + kbase + kq;
            uint32_t sb = sbase + (uint32_t)((buf * 2 * TILE + TILE + r * STRIDE + kq) * 4);
            CP_ASYNC16(sb, srcB);
        }
        CP_COMMIT();
    };

    issue_chunk(0, 0);

    for (int kc = 0; kc < NCH; kc++) {
        const int cur = kc & 1;
        CP_WAIT0();
        __syncthreads();
        if (kc + 1 < NCH) issue_chunk(kc + 1, cur ^ 1);

        const float* As = smem + cur * 2 * TILE;
        const float* Bs = As + TILE;

#pragma unroll
        for (int ks = 0; ks < 2; ks++) {          // K=16 per step
            const int k0 = ks * 16;
            // A fragments: 2 m16 tiles, hi/lo bf16 planes
            uint32_t ah[2][4], al[2][4];
#pragma unroll
            for (int tm = 0; tm < 2; tm++) {
                int r = warpM * 32 + tm * 16 + lq;
                float2 f0 = *reinterpret_cast<const float2*>(&As[r * STRIDE + k0 + lr * 2]);
                float2 f1 = *reinterpret_cast<const float2*>(&As[(r + 8) * STRIDE + k0 + lr * 2]);
                float2 f2 = *reinterpret_cast<const float2*>(&As[r * STRIDE + k0 + 8 + lr * 2]);
                float2 f3 = *reinterpret_cast<const float2*>(&As[(r + 8) * STRIDE + k0 + 8 + lr * 2]);
                float2 rm;
                ah[tm][0] = bf16x2_split(f0, rm); al[tm][0] = bf16x2_pack(rm);
                ah[tm][1] = bf16x2_split(f1, rm); al[tm][1] = bf16x2_pack(rm);
                ah[tm][2] = bf16x2_split(f2, rm); al[tm][2] = bf16x2_pack(rm);
                ah[tm][3] = bf16x2_split(f3, rm); al[tm][3] = bf16x2_pack(rm);
            }
#pragma unroll
            for (int tn = 0; tn < 8; tn++) {
                int n = warpN * 64 + tn * 8 + lq;
                float2 g0 = *reinterpret_cast<const float2*>(&Bs[n * STRIDE + k0 + lr * 2]);
                float2 g1 = *reinterpret_cast<const float2*>(&Bs[n * STRIDE + k0 + 8 + lr * 2]);
                float2 rm0, rm1;
                uint32_t bh0 = bf16x2_split(g0, rm0);
                uint32_t bh1 = bf16x2_split(g1, rm1);
                uint32_t bl0 = bf16x2_pack(rm0);
                uint32_t bl1 = bf16x2_pack(rm1);
                // 3-term split, interleaved across 2 independent accumulators
                MMA_BF16(acc[0][tn], ah[0][0], ah[0][1], ah[0][2], ah[0][3], bh0, bh1);
                MMA_BF16(acc[1][tn], ah[1][0], ah[1][1], ah[1][2], ah[1][3], bh0, bh1);
                MMA_BF16(acc[0][tn], al[0][0], al[0][1], al[0][2], al[0][3], bh0, bh1);
                MMA_BF16(acc[1][tn], al[1][0], al[1][1], al[1][2], al[1][3], bh0, bh1);
                MMA_BF16(acc[0][tn], ah[0][0], ah[0][1], ah[0][2], ah[0][3], bl0, bl1);
                MMA_BF16(acc[1][tn], ah[1][0], ah[1][1], ah[1][2], ah[1][3], bl0, bl1);
            }
        }
        __syncthreads();
    }

    // ---------------- epilogue ----------------
#pragma unroll
    for (int tn = 0; tn < 8; tn++) {
        int col = warpN * 64 + tn * 8 + lr * 2;
        float bx = bias[col], by = bias[col + 1];
#pragma unroll
        for (int tm = 0; tm < 2; tm++) {
            acc[tm][tn][0] += bx; acc[tm][tn][1] += by;
            acc[tm][tn][2] += bx; acc[tm][tn][3] += by;
        }
    }
    int rl[2][2], rg[2][2];
#pragma unroll
    for (int tm = 0; tm < 2; tm++) {
        rl[tm][0] = warpM * 32 + tm * 16 + lq;
        rl[tm][1] = rl[tm][0] + 8;
        rg[tm][0] = row0 + rl[tm][0];
        rg[tm][1] = row0 + rl[tm][1];
    }

    float* red0 = smem;
    float* red1 = smem + 128;

    if (MODE == 0) {
        float pa[2][2] = {{0,0},{0,0}}, pb[2][2] = {{0,0},{0,0}};
#pragma unroll
        for (int tn = 0; tn < 8; tn++) {
            int col = warpN * 64 + tn * 8 + lr * 2;
            float w0x = aux[col], w0y = aux[col + 1];
            float w1x = aux[128 + col], w1y = aux[128 + col + 1];
#pragma unroll
            for (int tm = 0; tm < 2; tm++) {
#pragma unroll
                for (int h = 0; h < 2; h++) {
                    float vx = acc[tm][tn][h * 2], vy = acc[tm][tn][h * 2 + 1];
                    if (rg[tm][h] < M)
                        *reinterpret_cast<float2*>(g_node_h + (size_t)rg[tm][h] * 128 + col)
                            = make_float2(vx, vy);
                    pa[tm][h] += vx * w0x + vy * w0y;
                    pb[tm][h] += vx * w1x + vy * w1y;
                }
            }
        }
        if (tid < 128) { red0[tid] = 0.f; red1[tid] = 0.f; }
        __syncthreads();
#pragma unroll
        for (int tm = 0; tm < 2; tm++)
#pragma unroll
            for (int h = 0; h < 2; h++) {
#pragma unroll
                for (int o = 1; o <= 2; o <<= 1) {
                    pa[tm][h] += __shfl_xor_sync(0xffffffffu, pa[tm][h], o);
                    pb[tm][h] += __shfl_xor_sync(0xffffffffu, pb[tm][h], o);
                }
                if (lr == 0) {
                    atomicAdd(&red0[rl[tm][h]], pa[tm][h]);
                    atomicAdd(&red1[rl[tm][h]], pb[tm][h]);
                }
            }
        __syncthreads();
        if (tid < 128 && row0 + tid < M) {
            g_a[row0 + tid] = red0[tid];
            g_b[row0 + tid] = red1[tid];
        }
    }
    else if (MODE == 1) {
        int dsts[2][2];
#pragma unroll
        for (int tm = 0; tm < 2; tm++)
#pragma unroll
            for (int h = 0; h < 2; h++)
                dsts[tm][h] = (rg[tm][h] < M) ? dst_idx[rg[tm][h]] : -1;

        float pd[2][2] = {{0,0},{0,0}};
#pragma unroll
        for (int tn = 0; tn < 8; tn++) {
            int col = warpN * 64 + tn * 8 + lr * 2;
            float w2x = aux[col], w2y = aux[col + 1];
#pragma unroll
            for (int tm = 0; tm < 2; tm++) {
#pragma unroll
                for (int h = 0; h < 2; h++) {
                    float vx = acc[tm][tn][h * 2], vy = acc[tm][tn][h * 2 + 1];
                    pd[tm][h] += vx * w2x + vy * w2y;
                    if (dsts[tm][h] >= 0)
                        atomicAdd(reinterpret_cast<float2*>(
                            g_agg_e + (size_t)dsts[tm][h] * 128 + col),
                            make_float2(vx, vy));
                }
            }
        }
        if (tid < 128) red0[tid] = 0.f;
        __syncthreads();
#pragma unroll
        for (int tm = 0; tm < 2; tm++)
#pragma unroll
            for (int h = 0; h < 2; h++) {
#pragma unroll
                for (int o = 1; o <= 2; o <<= 1)
                    pd[tm][h] += __shfl_xor_sync(0xffffffffu, pd[tm][h], o);
                if (lr == 0) atomicAdd(&red0[rl[tm][h]], pd[tm][h]);
            }
        __syncthreads();
        if (tid < 128 && row0 + tid < M)
            g_edot[row0 + tid] = red0[tid];
    }
    else {
        float ps[2][2] = {{0,0},{0,0}}, pq[2][2] = {{0,0},{0,0}};
#pragma unroll
        for (int tn = 0; tn < 8; tn++) {
            int col = warpN * 64 + tn * 8 + lr * 2;
#pragma unroll
            for (int tm = 0; tm < 2; tm++) {
#pragma unroll
                for (int h = 0; h < 2; h++) {
                    float2 res = (rg[tm][h] < M)
                        ? *reinterpret_cast<const float2*>(g_node_h + (size_t)rg[tm][h] * 128 + col)
                        : make_float2(0.f, 0.f);
                    float x0 = acc[tm][tn][h * 2] + res.x;
                    float x1 = acc[tm][tn][h * 2 + 1] + res.y;
                    acc[tm][tn][h * 2] = x0;
                    acc[tm][tn][h * 2 + 1] = x1;
                    ps[tm][h] += x0 + x1;
                    pq[tm][h] += x0 * x0 + x1 * x1;
                }
            }
        }
        if (tid < 128) { red0[tid] = 0.f; red1[tid] = 0.f; }
        __syncthreads();
#pragma unroll
        for (int tm = 0; tm < 2; tm++)
#pragma unroll
            for (int h = 0; h < 2; h++) {
#pragma unroll
                for (int o = 1; o <= 2; o <<= 1) {
                    ps[tm][h] += __shfl_xor_sync(0xffffffffu, ps[tm][h], o);
                    pq[tm][h] += __shfl_xor_sync(0xffffffffu, pq[tm][h], o);
                }
                if (lr == 0) {
                    atomicAdd(&red0[rl[tm][h]], ps[tm][h]);
                    atomicAdd(&red1[rl[tm][h]], pq[tm][h]);
                }
            }
        __syncthreads();
        float mean_[2][2], inv_[2][2];
#pragma unroll
        for (int tm = 0; tm < 2; tm++)
#pragma unroll
            for (int h = 0; h < 2; h++) {
                float m = red0[rl[tm][h]] * (1.f / 128.f);
                float var = red1[rl[tm][h]] * (1.f / 128.f) - m * m;
                mean_[tm][h] = m;
                inv_[tm][h] = rsqrtf(fmaxf(var, 0.f) + 1e-6f);
            }
        float pa[2][2] = {{0,0},{0,0}}, pb[2][2] = {{0,0},{0,0}};
#pragma unroll
        for (int tn = 0; tn < 8; tn++) {
            int col = warpN * 64 + tn * 8 + lr * 2;
            float scx = lns[col], scy = lns[col + 1];
            float bix = lnb[col], biy = lnb[col + 1];
            float w0x = aux[col], w0y = aux[col + 1];
            float w1x = aux[128 + col], w1y = aux[128 + col + 1];
#pragma unroll
            for (int tm = 0; tm < 2; tm++) {
#pragma unroll
                for (int h = 0; h < 2; h++) {
                    float y0 = fmaxf(0.f, (acc[tm][tn][h * 2] - mean_[tm][h]) * inv_[tm][h] * scx + bix);
                    float y1 = fmaxf(0.f, (acc[tm][tn][h * 2 + 1] - mean_[tm][h]) * inv_[tm][h] * scy + biy);
                    if (rg[tm][h] < M)
                        *reinterpret_cast<float2*>(dest + (size_t)rg[tm][h] * 128 + col)
                            = make_float2(y0, y1);
                    pa[tm][h] += y0 * w0x + y1 * w0y;
                    pb[tm][h] += y0 * w1x + y1 * w1y;
                }
            }
        }
        if (doab) {
            __syncthreads();
            if (tid < 128) { red0[tid] = 0.f; red1[tid] = 0.f; }
            __syncthreads();
#pragma unroll
            for (int tm = 0; tm < 2; tm++)
#pragma unroll
                for (int h = 0; h < 2; h++) {
#pragma unroll
                    for (int o = 1; o <= 2; o <<= 1) {
                        pa[tm][h] += __shfl_xor_sync(0xffffffffu, pa[tm][h], o);
                        pb[tm][h] += __shfl_xor_sync(0xffffffffu, pb[tm][h], o);
                    }
                    if (lr == 0) {
                        atomicAdd(&red0[rl[tm][h]], pa[tm][h]);
                        atomicAdd(&red1[rl[tm][h]], pb[tm][h]);
                    }
                }
            __syncthreads();
            if (tid < 128 && row0 + tid < M) {
                g_a[row0 + tid] = red0[tid];
                g_b[row0 + tid] = red1[tid];
            }
        }
    }
}

// ---------------- per-layer edge phase: gate + scatter src_f*wgt ----------------
__global__ void __launch_bounds__(256)
edge_kernel(const int* __restrict__ src_idx, const int* __restrict__ dst_idx,
            const float* __restrict__ b_top, float* __restrict__ w_out)
{
    int e = (blockIdx.x * blockDim.x + threadIdx.x) >> 5;
    int lane = threadIdx.x & 31;
    if (e >= NE) return;

    int s = src_idx[e];
    int d = dst_idx[e];

    float wgt;
    if (lane == 0) {
        float g = g_a[s] + g_b[d] + g_edot[e] + b_top[0];
        wgt = 1.f / (1.f + __expf(-g));
    }
    wgt = __shfl_sync(0xffffffffu, wgt, 0);

    float4 sv = *reinterpret_cast<const float4*>(g_node_h + (size_t)s * 128 + lane * 4);
    float4 msg = make_float4(sv.x * wgt, sv.y * wgt, sv.z * wgt, sv.w * wgt);
    atomicAdd(reinterpret_cast<float4*>(g_agg + (size_t)d * 128 + lane * 4), msg);

    if (w_out != nullptr && lane == 0) w_out[e] = wgt;
}

// ---------------- launch ----------------
extern "C" void kernel_launch(void* const* d_in, const int* in_sizes, int n_in,
                              void* d_out, int out_size)
{
    const float* nf     = (const float*)d_in[0];
    const float* ef     = (const float*)d_in[1];
    const int*   ei     = (const int*)  d_in[2];
    const float* W_node = (const float*)d_in[3];
    const float* b_node = (const float*)d_in[4];
    const float* W_edge = (const float*)d_in[5];
    const float* b_edge = (const float*)d_in[6];
    const float* W_gnn  = (const float*)d_in[7];
    const float* b_gnn  = (const float*)d_in[8];
    const float* W_top  = (const float*)d_in[9];
    const float* b_top  = (const float*)d_in[10];
    const float* ln_s   = (const float*)d_in[11];
    const float* ln_b   = (const float*)d_in[12];

    float* out       = (float*)d_out;
    float* out_nodes = out;
    float* out_w     = out + (size_t)NN * 128;

    const int* src = ei;
    const int* dst = ei + NE;

    const int SMEM_SZ = 4 * 128 * 36 * 4;   // 73728 B
    cudaFuncSetAttribute(mma_gemm_kernel<128, 0>, cudaFuncAttributeMaxDynamicSharedMemorySize, SMEM_SZ);
    cudaFuncSetAttribute(mma_gemm_kernel<64, 1>,  cudaFuncAttributeMaxDynamicSharedMemorySize, SMEM_SZ);
    cudaFuncSetAttribute(mma_gemm_kernel<256, 2>, cudaFuncAttributeMaxDynamicSharedMemorySize, SMEM_SZ);

    float* wtn = nullptr; float* wte = nullptr; float* wtg = nullptr;
    cudaGetSymbolAddress((void**)&wtn, g_wt_node);
    cudaGetSymbolAddress((void**)&wte, g_wt_edge);
    cudaGetSymbolAddress((void**)&wtg, g_wt_gnn);
    float* nodeh = nullptr;
    cudaGetSymbolAddress((void**)&nodeh, g_node_h);

    zero_agg_e_kernel<<<2048, 256>>>();
    transpose_node_kernel<<<(128 * 128 + 255) / 256, 256>>>(W_node);
    transpose_edge_kernel<<<(64 * 128 + 255) / 256, 256>>>(W_edge);
    transpose_gnn_kernel<<<(3 * 256 * 128 + 255) / 256, 256>>>(W_gnn);

    // node embed (+ a,b dots)
    mma_gemm_kernel<128, 0><<<(NN + 127) / 128, 256, SMEM_SZ>>>(
        nf, wtn, b_node, NN, W_top, nullptr, nullptr, nullptr, nullptr, 0);
    // edge embed (edot + agg_e; edge_h never materialized)
    mma_gemm_kernel<64, 1><<<(NE + 127) / 128, 256, SMEM_SZ>>>(
        ef, wte, b_edge, NE, W_top + 256, dst, nullptr, nullptr, nullptr, 0);

    for (int i = 0; i < 3; i++) {
        copy_agg_kernel<<<2048, 256>>>();
        edge_kernel<<<(NE * 32 + 255) / 256, 256>>>(
            src, dst, b_top, (i == 2) ? out_w : nullptr);
        mma_gemm_kernel<256, 2><<<(NN + 127) / 128, 256, SMEM_SZ>>>(
            nullptr, wtg + (size_t)i * 128 * 256, b_gnn + i * 128, NN,
            W_top, nullptr, ln_s + i * 128, ln_b + i * 128,
            (i == 2) ? out_nodes : nodeh, (i < 2) ? 1 : 0);
    }
}

// round 6
// speedup vs baseline: 1.7293x; 1.0266x over previous
#include <cuda_runtime.h>
#include <math.h>
#include <stdint.h>

#define NN 50000
#define NE 200000

// ---------------- scratch (device globals; no allocation) ----------------
__device__ float g_node_h[(size_t)NN * 128];
__device__ float g_agg[(size_t)NN * 128];     // per-layer scatter target (zeroed)
__device__ float g_agg_e[(size_t)NN * 128];   // layer-invariant: sum of edge_h into dst
__device__ float g_a[NN];                     // node_h . w0
__device__ float g_b[NN];                     // node_h . w1
__device__ float g_edot[NE];                  // edge_h . w2 (layer-invariant)
__device__ float g_wt_node[128 * 128];
__device__ float g_wt_edge[128 * 64];
__device__ float g_wt_gnn[3 * 128 * 256];

// ---------------- weight transposes ----------------
__global__ void transpose_node_kernel(const float* __restrict__ W)
{
    int i = blockIdx.x * blockDim.x + threadIdx.x;
    if (i < 128 * 128) { int k = i >> 7, n = i & 127; g_wt_node[n * 128 + k] = W[i]; }
}
__global__ void transpose_edge_kernel(const float* __restrict__ W)
{
    int i = blockIdx.x * blockDim.x + threadIdx.x;
    if (i < 64 * 128) { int k = i >> 7, n = i & 127; g_wt_edge[n * 64 + k] = W[i]; }
}
__global__ void transpose_gnn_kernel(const float* __restrict__ W)
{
    int i = blockIdx.x * blockDim.x + threadIdx.x;
    if (i < 3 * 256 * 128) {
        int l = i / 32768, r = i % 32768;
        int k = r >> 7, n = r & 127;
        g_wt_gnn[l * 32768 + n * 256 + k] = W[i];
    }
}

// ---------------- zero helpers ----------------
__global__ void zero_buf_kernel(float* __restrict__ p, int n4)
{
    float4 z = make_float4(0.f, 0.f, 0.f, 0.f);
    for (int i = blockIdx.x * blockDim.x + threadIdx.x; i < n4; i += gridDim.x * blockDim.x)
        reinterpret_cast<float4*>(p)[i] = z;
}

// ---------------- mma / ldmatrix / bf16 helpers ----------------
#define MMA_BF16(d, a0, a1, a2, a3, b0, b1)                                    \
    asm volatile(                                                              \
        "mma.sync.aligned.m16n8k16.row.col.f32.bf16.bf16.f32 "                 \
        "{%0,%1,%2,%3}, {%4,%5,%6,%7}, {%8,%9}, {%0,%1,%2,%3};"                \
        : "+f"((d)[0]), "+f"((d)[1]), "+f"((d)[2]), "+f"((d)[3])               \
        : "r"(a0), "r"(a1), "r"(a2), "r"(a3), "r"(b0), "r"(b1))

#define LDSM_X4(R, addr)                                                       \
    asm volatile("ldmatrix.sync.aligned.m8n8.x4.shared.b16 {%0,%1,%2,%3}, [%4];" \
        : "=r"((R)[0]), "=r"((R)[1]), "=r"((R)[2]), "=r"((R)[3]) : "r"(addr))

#define ST_V2(addr, x, y)                                                      \
    asm volatile("st.shared.v2.u32 [%0], {%1,%2};" :: "r"(addr), "r"(x), "r"(y))

// pack (f.x -> low, f.y -> high) bf16x2 and return fp32 remainder
__device__ __forceinline__ uint32_t bf16x2_split(float2 f, float2& rem) {
    uint32_t h;
    asm("cvt.rn.bf16x2.f32 %0, %1, %2;" : "=r"(h) : "f"(f.y), "f"(f.x));
    float hx = __uint_as_float(h << 16);
    float hy = __uint_as_float(h & 0xFFFF0000u);
    rem.x = f.x - hx;
    rem.y = f.y - hy;
    return h;
}
__device__ __forceinline__ uint32_t bf16x2_pack(float2 f) {
    uint32_t h;
    asm("cvt.rn.bf16x2.f32 %0, %1, %2;" : "=r"(h) : "f"(f.y), "f"(f.x));
    return h;
}

// =====================================================================
// Fused bf16x2-split GEMM with pre-split smem planes + ldmatrix.
// C[M,128] = A[M,KTOT] @ W + bias, fused epilogues:
// MODE 0 (node embed):  write g_node_h; a = y.w0, b = y.w1
// MODE 1 (edge embed):  NO C write; edot[e] = y.w2; atomicAdd rows into g_agg_e[dst]
// MODE 2 (update):      A = [node_h | g_agg + g_agg_e]; x = node_h + (acc+bias);
//                       LayerNorm+ReLU -> dest; opt a,b dots
// =====================================================================
template <int KTOT, int MODE>
__global__ void __launch_bounds__(256, 2)
mma_gemm_kernel(const float* __restrict__ A,
                const float* __restrict__ WT,
                const float* __restrict__ bias,
                int M,
                const float* __restrict__ aux,
                const int* __restrict__ dst_idx,
                const float* __restrict__ lns,
                const float* __restrict__ lnb,
                float* __restrict__ dest,
                int doab)
{
    extern __shared__ float smem[];
    constexpr int NCH = KTOT / 32;
    // bf16 planes: 128 rows x 40 bf16 (32 data + 8 pad) = 80 B pitch
    constexpr int PITCH = 80;
    constexpr int PLANE = 128 * PITCH;         // 10240 B
    constexpr int OFF_AH = 0, OFF_AL = PLANE, OFF_BH = 2 * PLANE, OFF_BL = 3 * PLANE;
    constexpr int BUF = 4 * PLANE;             // 40960 B per buffer

    const int tid   = threadIdx.x;
    const int wid   = tid >> 5;
    const int lane  = tid & 31;
    const int warpM = wid >> 1;
    const int warpN = wid & 1;
    const int lq    = lane >> 2;
    const int lr    = lane & 3;
    const int row0  = blockIdx.x * 128;

    const uint32_t sbase = (uint32_t)__cvta_generic_to_shared(smem);

    float acc[2][8][4];
#pragma unroll
    for (int i = 0; i < 2; i++)
#pragma unroll
        for (int j = 0; j < 8; j++)
#pragma unroll
            for (int q = 0; q < 4; q++) acc[i][j][q] = 0.f;

    // fill one K-chunk into plane buffer `buf` (convert each element once)
    auto fill = [&](int kc, int buf) {
        const int kbase = kc * 32;
        const uint32_t bufo = sbase + buf * BUF;
#pragma unroll
        for (int l = 0; l < 4; l++) {
            int idx = tid + l * 256;
            int r = idx >> 3;
            int kq = (idx & 7) * 4;
            int grow = row0 + r;
            if (grow >= M) grow = M - 1;
            float4 va;
            if (MODE == 2) {
                int kg = kbase + kq;
                if (kg < 128) {
                    va = *reinterpret_cast<const float4*>(g_node_h + (size_t)grow * 128 + kg);
                } else {
                    float4 x = *reinterpret_cast<const float4*>(g_agg + (size_t)grow * 128 + (kg - 128));
                    float4 y = *reinterpret_cast<const float4*>(g_agg_e + (size_t)grow * 128 + (kg - 128));
                    va = make_float4(x.x + y.x, x.y + y.y, x.z + y.z, x.w + y.w);
                }
            } else {
                va = *reinterpret_cast<const float4*>(A + (size_t)grow * KTOT + kbase + kq);
            }
            float4 vb = *reinterpret_cast<const float4*>(WT + (size_t)r * KTOT + kbase + kq);

            uint32_t off = (uint32_t)(r * PITCH + kq * 2);
            float2 rm0, rm1;
            uint32_t h0 = bf16x2_split(make_float2(va.x, va.y), rm0);
            uint32_t h1 = bf16x2_split(make_float2(va.z, va.w), rm1);
            ST_V2(bufo + OFF_AH + off, h0, h1);
            ST_V2(bufo + OFF_AL + off, bf16x2_pack(rm0), bf16x2_pack(rm1));
            h0 = bf16x2_split(make_float2(vb.x, vb.y), rm0);
            h1 = bf16x2_split(make_float2(vb.z, vb.w), rm1);
            ST_V2(bufo + OFF_BH + off, h0, h1);
            ST_V2(bufo + OFF_BL + off, bf16x2_pack(rm0), bf16x2_pack(rm1));
        }
    };

    fill(0, 0);
    __syncthreads();

    const int g  = lane & 15;           // ldmatrix A row select
    const int hh = lane >> 4;           // 0: k0-7, 1: k8-15
    const int q8  = lane & 7;           // ldmatrix B row select
    const int seg = (lane >> 3) & 3;

    for (int kc = 0; kc < NCH; kc++) {
        const int cur = kc & 1;
        if (kc + 1 < NCH) fill(kc + 1, cur ^ 1);

        const uint32_t bufo = sbase + cur * BUF;
#pragma unroll
        for (int ks = 0; ks < 2; ks++) {
            uint32_t ah[2][4], al[2][4];
#pragma unroll
            for (int tm = 0; tm < 2; tm++) {
                uint32_t ra = bufo + OFF_AH
                    + (uint32_t)((warpM * 32 + tm * 16 + g) * PITCH + ks * 32 + hh * 16);
                LDSM_X4(ah[tm], ra);
                LDSM_X4(al[tm], ra + (OFF_AL - OFF_AH));
            }
#pragma unroll
            for (int p = 0; p < 4; p++) {
                int n = warpN * 64 + (2 * p + (seg >> 1)) * 8 + q8;
                uint32_t rb = bufo + OFF_BH
                    + (uint32_t)(n * PITCH + ks * 32 + (seg & 1) * 16);
                uint32_t bh[4], bl[4];
                LDSM_X4(bh, rb);
                LDSM_X4(bl, rb + (OFF_BL - OFF_BH));
                // 12 MMAs, acc chains spaced 4 apart
                MMA_BF16(acc[0][2 * p],     ah[0][0], ah[0][1], ah[0][2], ah[0][3], bh[0], bh[1]);
                MMA_BF16(acc[1][2 * p],     ah[1][0], ah[1][1], ah[1][2], ah[1][3], bh[0], bh[1]);
                MMA_BF16(acc[0][2 * p + 1], ah[0][0], ah[0][1], ah[0][2], ah[0][3], bh[2], bh[3]);
                MMA_BF16(acc[1][2 * p + 1], ah[1][0], ah[1][1], ah[1][2], ah[1][3], bh[2], bh[3]);
                MMA_BF16(acc[0][2 * p],     al[0][0], al[0][1], al[0][2], al[0][3], bh[0], bh[1]);
                MMA_BF16(acc[1][2 * p],     al[1][0], al[1][1], al[1][2], al[1][3], bh[0], bh[1]);
                MMA_BF16(acc[0][2 * p + 1], al[0][0], al[0][1], al[0][2], al[0][3], bh[2], bh[3]);
                MMA_BF16(acc[1][2 * p + 1], al[1][0], al[1][1], al[1][2], al[1][3], bh[2], bh[3]);
                MMA_BF16(acc[0][2 * p],     ah[0][0], ah[0][1], ah[0][2], ah[0][3], bl[0], bl[1]);
                MMA_BF16(acc[1][2 * p],     ah[1][0], ah[1][1], ah[1][2], ah[1][3], bl[0], bl[1]);
                MMA_BF16(acc[0][2 * p + 1], ah[0][0], ah[0][1], ah[0][2], ah[0][3], bl[2], bl[3]);
                MMA_BF16(acc[1][2 * p + 1], ah[1][0], ah[1][1], ah[1][2], ah[1][3], bl[2], bl[3]);
            }
        }
        __syncthreads();
    }

    // ---------------- epilogue ----------------
#pragma unroll
    for (int tn = 0; tn < 8; tn++) {
        int col = warpN * 64 + tn * 8 + lr * 2;
        float bx = bias[col], by = bias[col + 1];
#pragma unroll
        for (int tm = 0; tm < 2; tm++) {
            acc[tm][tn][0] += bx; acc[tm][tn][1] += by;
            acc[tm][tn][2] += bx; acc[tm][tn][3] += by;
        }
    }
    int rl[2][2], rg[2][2];
#pragma unroll
    for (int tm = 0; tm < 2; tm++) {
        rl[tm][0] = warpM * 32 + tm * 16 + lq;
        rl[tm][1] = rl[tm][0] + 8;
        rg[tm][0] = row0 + rl[tm][0];
        rg[tm][1] = row0 + rl[tm][1];
    }

    float* red0 = smem;
    float* red1 = smem + 128;

    if (MODE == 0) {
        float pa[2][2] = {{0,0},{0,0}}, pb[2][2] = {{0,0},{0,0}};
#pragma unroll
        for (int tn = 0; tn < 8; tn++) {
            int col = warpN * 64 + tn * 8 + lr * 2;
            float w0x = aux[col], w0y = aux[col + 1];
            float w1x = aux[128 + col], w1y = aux[128 + col + 1];
#pragma unroll
            for (int tm = 0; tm < 2; tm++) {
#pragma unroll
                for (int h = 0; h < 2; h++) {
                    float vx = acc[tm][tn][h * 2], vy = acc[tm][tn][h * 2 + 1];
                    if (rg[tm][h] < M)
                        *reinterpret_cast<float2*>(g_node_h + (size_t)rg[tm][h] * 128 + col)
                            = make_float2(vx, vy);
                    pa[tm][h] += vx * w0x + vy * w0y;
                    pb[tm][h] += vx * w1x + vy * w1y;
                }
            }
        }
        if (tid < 128) { red0[tid] = 0.f; red1[tid] = 0.f; }
        __syncthreads();
#pragma unroll
        for (int tm = 0; tm < 2; tm++)
#pragma unroll
            for (int h = 0; h < 2; h++) {
#pragma unroll
                for (int o = 1; o <= 2; o <<= 1) {
                    pa[tm][h] += __shfl_xor_sync(0xffffffffu, pa[tm][h], o);
                    pb[tm][h] += __shfl_xor_sync(0xffffffffu, pb[tm][h], o);
                }
                if (lr == 0) {
                    atomicAdd(&red0[rl[tm][h]], pa[tm][h]);
                    atomicAdd(&red1[rl[tm][h]], pb[tm][h]);
                }
            }
        __syncthreads();
        if (tid < 128 && row0 + tid < M) {
            g_a[row0 + tid] = red0[tid];
            g_b[row0 + tid] = red1[tid];
        }
    }
    else if (MODE == 1) {
        int dsts[2][2];
#pragma unroll
        for (int tm = 0; tm < 2; tm++)
#pragma unroll
            for (int h = 0; h < 2; h++)
                dsts[tm][h] = (rg[tm][h] < M) ? dst_idx[rg[tm][h]] : -1;

        float pd[2][2] = {{0,0},{0,0}};
#pragma unroll
        for (int tn = 0; tn < 8; tn++) {
            int col = warpN * 64 + tn * 8 + lr * 2;
            float w2x = aux[col], w2y = aux[col + 1];
#pragma unroll
            for (int tm = 0; tm < 2; tm++) {
#pragma unroll
                for (int h = 0; h < 2; h++) {
                    float vx = acc[tm][tn][h * 2], vy = acc[tm][tn][h * 2 + 1];
                    pd[tm][h] += vx * w2x + vy * w2y;
                    if (dsts[tm][h] >= 0)
                        atomicAdd(reinterpret_cast<float2*>(
                            g_agg_e + (size_t)dsts[tm][h] * 128 + col),
                            make_float2(vx, vy));
                }
            }
        }
        if (tid < 128) red0[tid] = 0.f;
        __syncthreads();
#pragma unroll
        for (int tm = 0; tm < 2; tm++)
#pragma unroll
            for (int h = 0; h < 2; h++) {
#pragma unroll
                for (int o = 1; o <= 2; o <<= 1)
                    pd[tm][h] += __shfl_xor_sync(0xffffffffu, pd[tm][h], o);
                if (lr == 0) atomicAdd(&red0[rl[tm][h]], pd[tm][h]);
            }
        __syncthreads();
        if (tid < 128 && row0 + tid < M)
            g_edot[row0 + tid] = red0[tid];
    }
    else {
        float ps[2][2] = {{0,0},{0,0}}, pq[2][2] = {{0,0},{0,0}};
#pragma unroll
        for (int tn = 0; tn < 8; tn++) {
            int col = warpN * 64 + tn * 8 + lr * 2;
#pragma unroll
            for (int tm = 0; tm < 2; tm++) {
#pragma unroll
                for (int h = 0; h < 2; h++) {
                    float2 res = (rg[tm][h] < M)
                        ? *reinterpret_cast<const float2*>(g_node_h + (size_t)rg[tm][h] * 128 + col)
                        : make_float2(0.f, 0.f);
                    float x0 = acc[tm][tn][h * 2] + res.x;
                    float x1 = acc[tm][tn][h * 2 + 1] + res.y;
                    acc[tm][tn][h * 2] = x0;
                    acc[tm][tn][h * 2 + 1] = x1;
                    ps[tm][h] += x0 + x1;
                    pq[tm][h] += x0 * x0 + x1 * x1;
                }
            }
        }
        if (tid < 128) { red0[tid] = 0.f; red1[tid] = 0.f; }
        __syncthreads();
#pragma unroll
        for (int tm = 0; tm < 2; tm++)
#pragma unroll
            for (int h = 0; h < 2; h++) {
#pragma unroll
                for (int o = 1; o <= 2; o <<= 1) {
                    ps[tm][h] += __shfl_xor_sync(0xffffffffu, ps[tm][h], o);
                    pq[tm][h] += __shfl_xor_sync(0xffffffffu, pq[tm][h], o);
                }
                if (lr == 0) {
                    atomicAdd(&red0[rl[tm][h]], ps[tm][h]);
                    atomicAdd(&red1[rl[tm][h]], pq[tm][h]);
                }
            }
        __syncthreads();
        float mean_[2][2], inv_[2][2];
#pragma unroll
        for (int tm = 0; tm < 2; tm++)
#pragma unroll
            for (int h = 0; h < 2; h++) {
                float m = red0[rl[tm][h]] * (1.f / 128.f);
                float var = red1[rl[tm][h]] * (1.f / 128.f) - m * m;
                mean_[tm][h] = m;
                inv_[tm][h] = rsqrtf(fmaxf(var, 0.f) + 1e-6f);
            }
        float pa[2][2] = {{0,0},{0,0}}, pb[2][2] = {{0,0},{0,0}};
#pragma unroll
        for (int tn = 0; tn < 8; tn++) {
            int col = warpN * 64 + tn * 8 + lr * 2;
            float scx = lns[col], scy = lns[col + 1];
            float bix = lnb[col], biy = lnb[col + 1];
            float w0x = aux[col], w0y = aux[col + 1];
            float w1x = aux[128 + col], w1y = aux[128 + col + 1];
#pragma unroll
            for (int tm = 0; tm < 2; tm++) {
#pragma unroll
                for (int h = 0; h < 2; h++) {
                    float y0 = fmaxf(0.f, (acc[tm][tn][h * 2] - mean_[tm][h]) * inv_[tm][h] * scx + bix);
                    float y1 = fmaxf(0.f, (acc[tm][tn][h * 2 + 1] - mean_[tm][h]) * inv_[tm][h] * scy + biy);
                    if (rg[tm][h] < M)
                        *reinterpret_cast<float2*>(dest + (size_t)rg[tm][h] * 128 + col)
                            = make_float2(y0, y1);
                    pa[tm][h] += y0 * w0x + y1 * w0y;
                    pb[tm][h] += y0 * w1x + y1 * w1y;
                }
            }
        }
        if (doab) {
            __syncthreads();
            if (tid < 128) { red0[tid] = 0.f; red1[tid] = 0.f; }
            __syncthreads();
#pragma unroll
            for (int tm = 0; tm < 2; tm++)
#pragma unroll
                for (int h = 0; h < 2; h++) {
#pragma unroll
                    for (int o = 1; o <= 2; o <<= 1) {
                        pa[tm][h] += __shfl_xor_sync(0xffffffffu, pa[tm][h], o);
                        pb[tm][h] += __shfl_xor_sync(0xffffffffu, pb[tm][h], o);
                    }
                    if (lr == 0) {
                        atomicAdd(&red0[rl[tm][h]], pa[tm][h]);
                        atomicAdd(&red1[rl[tm][h]], pb[tm][h]);
                    }
                }
            __syncthreads();
            if (tid < 128 && row0 + tid < M) {
                g_a[row0 + tid] = red0[tid];
                g_b[row0 + tid] = red1[tid];
            }
        }
    }
}

// ---------------- per-layer edge phase: gate + scatter src_f*wgt ----------------
__global__ void __launch_bounds__(256)
edge_kernel(const int* __restrict__ src_idx, const int* __restrict__ dst_idx,
            const float* __restrict__ b_top, float* __restrict__ w_out)
{
    int e = (blockIdx.x * blockDim.x + threadIdx.x) >> 5;
    int lane = threadIdx.x & 31;
    if (e >= NE) return;

    int s = src_idx[e];
    int d = dst_idx[e];

    float wgt;
    if (lane == 0) {
        float g = g_a[s] + g_b[d] + g_edot[e] + b_top[0];
        wgt = 1.f / (1.f + __expf(-g));
    }
    wgt = __shfl_sync(0xffffffffu, wgt, 0);

    float4 sv = *reinterpret_cast<const float4*>(g_node_h + (size_t)s * 128 + lane * 4);
    float4 msg = make_float4(sv.x * wgt, sv.y * wgt, sv.z * wgt, sv.w * wgt);
    atomicAdd(reinterpret_cast<float4*>(g_agg + (size_t)d * 128 + lane * 4), msg);

    if (w_out != nullptr && lane == 0) w_out[e] = wgt;
}

// ---------------- launch ----------------
extern "C" void kernel_launch(void* const* d_in, const int* in_sizes, int n_in,
                              void* d_out, int out_size)
{
    const float* nf     = (const float*)d_in[0];
    const float* ef     = (const float*)d_in[1];
    const int*   ei     = (const int*)  d_in[2];
    const float* W_node = (const float*)d_in[3];
    const float* b_node = (const float*)d_in[4];
    const float* W_edge = (const float*)d_in[5];
    const float* b_edge = (const float*)d_in[6];
    const float* W_gnn  = (const float*)d_in[7];
    const float* b_gnn  = (const float*)d_in[8];
    const float* W_top  = (const float*)d_in[9];
    const float* b_top  = (const float*)d_in[10];
    const float* ln_s   = (const float*)d_in[11];
    const float* ln_b   = (const float*)d_in[12];

    float* out       = (float*)d_out;
    float* out_nodes = out;
    float* out_w     = out + (size_t)NN * 128;

    const int* src = ei;
    const int* dst = ei + NE;

    const int SMEM_SZ = 2 * 4 * 128 * 80;   // 81920 B
    cudaFuncSetAttribute(mma_gemm_kernel<128, 0>, cudaFuncAttributeMaxDynamicSharedMemorySize, SMEM_SZ);
    cudaFuncSetAttribute(mma_gemm_kernel<64, 1>,  cudaFuncAttributeMaxDynamicSharedMemorySize, SMEM_SZ);
    cudaFuncSetAttribute(mma_gemm_kernel<256, 2>, cudaFuncAttributeMaxDynamicSharedMemorySize, SMEM_SZ);

    float* wtn = nullptr; float* wte = nullptr; float* wtg = nullptr;
    cudaGetSymbolAddress((void**)&wtn, g_wt_node);
    cudaGetSymbolAddress((void**)&wte, g_wt_edge);
    cudaGetSymbolAddress((void**)&wtg, g_wt_gnn);
    float* nodeh = nullptr; float* aggp = nullptr; float* aggep = nullptr;
    cudaGetSymbolAddress((void**)&nodeh, g_node_h);
    cudaGetSymbolAddress((void**)&aggp, g_agg);
    cudaGetSymbolAddress((void**)&aggep, g_agg_e);

    zero_buf_kernel<<<1024, 256>>>(aggep, NN * 128 / 4);
    transpose_node_kernel<<<(128 * 128 + 255) / 256, 256>>>(W_node);
    transpose_edge_kernel<<<(64 * 128 + 255) / 256, 256>>>(W_edge);
    transpose_gnn_kernel<<<(3 * 256 * 128 + 255) / 256, 256>>>(W_gnn);

    // node embed (+ a,b dots)
    mma_gemm_kernel<128, 0><<<(NN + 127) / 128, 256, SMEM_SZ>>>(
        nf, wtn, b_node, NN, W_top, nullptr, nullptr, nullptr, nullptr, 0);
    // edge embed (edot + agg_e; edge_h never materialized)
    mma_gemm_kernel<64, 1><<<(NE + 127) / 128, 256, SMEM_SZ>>>(
        ef, wte, b_edge, NE, W_top + 256, dst, nullptr, nullptr, nullptr, 0);

    for (int i = 0; i < 3; i++) {
        zero_buf_kernel<<<1024, 256>>>(aggp, NN * 128 / 4);
        edge_kernel<<<(NE * 32 + 255) / 256, 256>>>(
            src, dst, b_top, (i == 2) ? out_w : nullptr);
        mma_gemm_kernel<256, 2><<<(NN + 127) / 128, 256, SMEM_SZ>>>(
            nullptr, wtg + (size_t)i * 128 * 256, b_gnn + i * 128, NN,
            W_top, nullptr, ln_s + i * 128, ln_b + i * 128,
            (i == 2) ? out_nodes : nodeh, (i < 2) ? 1 : 0);
    }
}

// round 7
// speedup vs baseline: 1.7896x; 1.0349x over previous
#include <cuda_runtime.h>
#include <cuda_bf16.h>
#include <math.h>
#include <stdint.h>

#define NN 50000
#define NE 200000

// ---------------- scratch (device globals; no allocation) ----------------
__device__ float g_node_h[(size_t)NN * 128];
__device__ float g_agg[(size_t)NN * 128];     // per-layer: agg_e copy + scatter
__device__ float g_agg_e[(size_t)NN * 128];   // layer-invariant: sum of edge_h into dst
__device__ float g_a[NN];                     // node_h . w0
__device__ float g_b[NN];                     // node_h . w1
__device__ float g_edot[NE];                  // edge_h . w2 (layer-invariant)
// pre-split bf16 weight planes, [n][k] layout (B operand, col-major)
__device__ __nv_bfloat16 g_wth_node[128 * 128], g_wtl_node[128 * 128];
__device__ __nv_bfloat16 g_wth_edge[128 * 64],  g_wtl_edge[128 * 64];
__device__ __nv_bfloat16 g_wth_gnn[3 * 128 * 256], g_wtl_gnn[3 * 128 * 256];

// ---------------- weight transpose + split ----------------
__device__ __forceinline__ void split_store(float x, __nv_bfloat16* ph, __nv_bfloat16* pl) {
    __nv_bfloat16 h = __float2bfloat16(x);
    *ph = h;
    *pl = __float2bfloat16(x - __bfloat162float(h));
}
__global__ void transpose_node_kernel(const float* __restrict__ W)
{
    int i = blockIdx.x * blockDim.x + threadIdx.x;
    if (i < 128 * 128) {
        int k = i >> 7, n = i & 127;
        split_store(W[i], &g_wth_node[n * 128 + k], &g_wtl_node[n * 128 + k]);
    }
}
__global__ void transpose_edge_kernel(const float* __restrict__ W)
{
    int i = blockIdx.x * blockDim.x + threadIdx.x;
    if (i < 64 * 128) {
        int k = i >> 7, n = i & 127;
        split_store(W[i], &g_wth_edge[n * 64 + k], &g_wtl_edge[n * 64 + k]);
    }
}
__global__ void transpose_gnn_kernel(const float* __restrict__ W)
{
    int i = blockIdx.x * blockDim.x + threadIdx.x;
    if (i < 3 * 256 * 128) {
        int l = i / 32768, r = i % 32768;
        int k = r >> 7, n = r & 127;
        split_store(W[i], &g_wth_gnn[l * 32768 + n * 256 + k],
                          &g_wtl_gnn[l * 32768 + n * 256 + k]);
    }
}

// ---------------- zero / copy helpers ----------------
__global__ void zero_buf_kernel(float* __restrict__ p, int n4)
{
    float4 z = make_float4(0.f, 0.f, 0.f, 0.f);
    for (int i = blockIdx.x * blockDim.x + threadIdx.x; i < n4; i += gridDim.x * blockDim.x)
        reinterpret_cast<float4*>(p)[i] = z;
}
__global__ void copy_agg_kernel()   // g_agg = g_agg_e
{
    const int n4 = NN * 128 / 4;
    for (int i = blockIdx.x * blockDim.x + threadIdx.x; i < n4; i += gridDim.x * blockDim.x)
        reinterpret_cast<float4*>(g_agg)[i] = reinterpret_cast<const float4*>(g_agg_e)[i];
}

// ---------------- mma / ldmatrix / cp.async / bf16 helpers ----------------
#define MMA_BF16(d, a0, a1, a2, a3, b0, b1)                                    \
    asm volatile(                                                              \
        "mma.sync.aligned.m16n8k16.row.col.f32.bf16.bf16.f32 "                 \
        "{%0,%1,%2,%3}, {%4,%5,%6,%7}, {%8,%9}, {%0,%1,%2,%3};"                \
        : "+f"((d)[0]), "+f"((d)[1]), "+f"((d)[2]), "+f"((d)[3])               \
        : "r"(a0), "r"(a1), "r"(a2), "r"(a3), "r"(b0), "r"(b1))

#define LDSM_X4(R, addr)                                                       \
    asm volatile("ldmatrix.sync.aligned.m8n8.x4.shared.b16 {%0,%1,%2,%3}, [%4];" \
        : "=r"((R)[0]), "=r"((R)[1]), "=r"((R)[2]), "=r"((R)[3]) : "r"(addr))

#define ST_V2(addr, x, y)                                                      \
    asm volatile("st.shared.v2.u32 [%0], {%1,%2};" :: "r"(addr), "r"(x), "r"(y))

#define CP_ASYNC16(saddr, gptr) \
    asm volatile("cp.async.cg.shared.global [%0], [%1], 16;" :: "r"(saddr), "l"(gptr))
#define CP_COMMIT() asm volatile("cp.async.commit_group;")
#define CP_WAIT0()  asm volatile("cp.async.wait_group 0;")

__device__ __forceinline__ uint32_t bf16x2_split(float2 f, float2& rem) {
    uint32_t h;
    asm("cvt.rn.bf16x2.f32 %0, %1, %2;" : "=r"(h) : "f"(f.y), "f"(f.x));
    float hx = __uint_as_float(h << 16);
    float hy = __uint_as_float(h & 0xFFFF0000u);
    rem.x = f.x - hx;
    rem.y = f.y - hy;
    return h;
}
__device__ __forceinline__ uint32_t bf16x2_pack(float2 f) {
    uint32_t h;
    asm("cvt.rn.bf16x2.f32 %0, %1, %2;" : "=r"(h) : "f"(f.y), "f"(f.x));
    return h;
}

// =====================================================================
// Fused bf16x2-split GEMM, pre-split B planes via cp.async, A via
// register-staged LDG converted AFTER the MMA loop (latency hidden).
// MODE 0 (node embed):  write g_node_h; a = y.w0, b = y.w1
// MODE 1 (edge embed):  NO C write; edot[e] = y.w2; atomicAdd rows into g_agg_e[dst]
// MODE 2 (update):      A = [node_h | g_agg]; x = node_h + (acc+bias);
//                       LayerNorm+ReLU -> dest; opt a,b dots
// =====================================================================
template <int KTOT, int MODE>
__global__ void __launch_bounds__(256, 2)
mma_gemm_kernel(const float* __restrict__ A,
                const __nv_bfloat16* __restrict__ WTH,
                const __nv_bfloat16* __restrict__ WTL,
                const float* __restrict__ bias,
                int M,
                const float* __restrict__ aux,
                const int* __restrict__ dst_idx,
                const float* __restrict__ lns,
                const float* __restrict__ lnb,
                float* __restrict__ dest,
                int doab)
{
    extern __shared__ float smem[];
    constexpr int NCH = KTOT / 32;
    constexpr int PITCH = 80;                  // bytes per 32-bf16 row (64 data + 16 pad)
    constexpr int PLANE = 128 * PITCH;         // 10240 B
    constexpr int OFF_AH = 0, OFF_AL = PLANE, OFF_BH = 2 * PLANE, OFF_BL = 3 * PLANE;
    constexpr int BUF = 4 * PLANE;             // 40960 B per buffer

    const int tid   = threadIdx.x;
    const int wid   = tid >> 5;
    const int lane  = tid & 31;
    const int warpM = wid >> 1;
    const int warpN = wid & 1;
    const int lq    = lane >> 2;
    const int lr    = lane & 3;
    const int row0  = blockIdx.x * 128;

    const uint32_t sbase = (uint32_t)__cvta_generic_to_shared(smem);

    float acc[2][8][4];
#pragma unroll
    for (int i = 0; i < 2; i++)
#pragma unroll
        for (int j = 0; j < 8; j++)
#pragma unroll
            for (int q = 0; q < 4; q++) acc[i][j][q] = 0.f;

    // ---- A: register-staged loads (4 x float4 per thread) ----
    float4 va[4];
    auto loadA = [&](int kc) {
#pragma unroll
        for (int l = 0; l < 4; l++) {
            int idx = tid + l * 256;
            int r = idx >> 3;
            int kq = (idx & 7) * 4;
            int grow = row0 + r;
            if (grow >= M) grow = M - 1;
            const float* src;
            if (MODE == 2)
                src = (kc < 4) ? g_node_h + (size_t)grow * 128 + kc * 32 + kq
                               : g_agg + (size_t)grow * 128 + (kc - 4) * 32 + kq;
            else
                src = A + (size_t)grow * KTOT + kc * 32 + kq;
            va[l] = *reinterpret_cast<const float4*>(src);
        }
    };
    auto storeA = [&](int buf) {
        const uint32_t bufo = sbase + buf * BUF;
#pragma unroll
        for (int l = 0; l < 4; l++) {
            int idx = tid + l * 256;
            int r = idx >> 3;
            int kq = (idx & 7) * 4;
            uint32_t off = (uint32_t)(r * PITCH + kq * 2);
            float2 rm0, rm1;
            uint32_t h0 = bf16x2_split(make_float2(va[l].x, va[l].y), rm0);
            uint32_t h1 = bf16x2_split(make_float2(va[l].z, va[l].w), rm1);
            ST_V2(bufo + OFF_AH + off, h0, h1);
            ST_V2(bufo + OFF_AL + off, bf16x2_pack(rm0), bf16x2_pack(rm1));
        }
    };
    // ---- B: pure cp.async from pre-split planes (2 granules/plane/thread) ----
    auto fillB = [&](int kc, int buf) {
        const uint32_t bufo = sbase + buf * BUF;
#pragma unroll
        for (int l = 0; l < 2; l++) {
            int gr = tid + l * 256;            // 512 granules per plane
            int row = gr >> 2;
            int seg = gr & 3;
            uint32_t soff = (uint32_t)(row * PITCH + seg * 16);
            const __nv_bfloat16* sh = WTH + (size_t)row * KTOT + kc * 32 + seg * 8;
            const __nv_bfloat16* sl = WTL + (size_t)row * KTOT + kc * 32 + seg * 8;
            CP_ASYNC16(bufo + OFF_BH + soff, sh);
            CP_ASYNC16(bufo + OFF_BL + soff, sl);
        }
        CP_COMMIT();
    };

    // prologue
    loadA(0);
    fillB(0, 0);
    storeA(0);
    CP_WAIT0();
    __syncthreads();

    const int g   = lane & 15;
    const int hh  = lane >> 4;
    const int q8  = lane & 7;
    const int seg = (lane >> 3) & 3;

    for (int kc = 0; kc < NCH; kc++) {
        const int cur = kc & 1;
        if (kc + 1 < NCH) {
            loadA(kc + 1);        // LDGs issued; consumed after MMA loop
            fillB(kc + 1, cur ^ 1);
        }

        const uint32_t bufo = sbase + cur * BUF;
#pragma unroll
        for (int ks = 0; ks < 2; ks++) {
            uint32_t ah[2][4], al[2][4];
#pragma unroll
            for (int tm = 0; tm < 2; tm++) {
                uint32_t ra = bufo + OFF_AH
                    + (uint32_t)((warpM * 32 + tm * 16 + g) * PITCH + ks * 32 + hh * 16);
                LDSM_X4(ah[tm], ra);
                LDSM_X4(al[tm], ra + (OFF_AL - OFF_AH));
            }
#pragma unroll
            for (int p = 0; p < 4; p++) {
                int n = warpN * 64 + (2 * p + (seg >> 1)) * 8 + q8;
                uint32_t rb = bufo + OFF_BH
                    + (uint32_t)(n * PITCH + ks * 32 + (seg & 1) * 16);
                uint32_t bh[4], bl[4];
                LDSM_X4(bh, rb);
                LDSM_X4(bl, rb + (OFF_BL - OFF_BH));
                MMA_BF16(acc[0][2 * p],     ah[0][0], ah[0][1], ah[0][2], ah[0][3], bh[0], bh[1]);
                MMA_BF16(acc[1][2 * p],     ah[1][0], ah[1][1], ah[1][2], ah[1][3], bh[0], bh[1]);
                MMA_BF16(acc[0][2 * p + 1], ah[0][0], ah[0][1], ah[0][2], ah[0][3], bh[2], bh[3]);
                MMA_BF16(acc[1][2 * p + 1], ah[1][0], ah[1][1], ah[1][2], ah[1][3], bh[2], bh[3]);
                MMA_BF16(acc[0][2 * p],     al[0][0], al[0][1], al[0][2], al[0][3], bh[0], bh[1]);
                MMA_BF16(acc[1][2 * p],     al[1][0], al[1][1], al[1][2], al[1][3], bh[0], bh[1]);
                MMA_BF16(acc[0][2 * p + 1], al[0][0], al[0][1], al[0][2], al[0][3], bh[2], bh[3]);
                MMA_BF16(acc[1][2 * p + 1], al[1][0], al[1][1], al[1][2], al[1][3], bh[2], bh[3]);
                MMA_BF16(acc[0][2 * p],     ah[0][0], ah[0][1], ah[0][2], ah[0][3], bl[0], bl[1]);
                MMA_BF16(acc[1][2 * p],     ah[1][0], ah[1][1], ah[1][2], ah[1][3], bl[0], bl[1]);
                MMA_BF16(acc[0][2 * p + 1], ah[0][0], ah[0][1], ah[0][2], ah[0][3], bl[2], bl[3]);
                MMA_BF16(acc[1][2 * p + 1], ah[1][0], ah[1][1], ah[1][2], ah[1][3], bl[2], bl[3]);
            }
        }
        if (kc + 1 < NCH) storeA(cur ^ 1);
        CP_WAIT0();
        __syncthreads();
    }

    // ---------------- epilogue ----------------
#pragma unroll
    for (int tn = 0; tn < 8; tn++) {
        int col = warpN * 64 + tn * 8 + lr * 2;
        float bx = bias[col], by = bias[col + 1];
#pragma unroll
        for (int tm = 0; tm < 2; tm++) {
            acc[tm][tn][0] += bx; acc[tm][tn][1] += by;
            acc[tm][tn][2] += bx; acc[tm][tn][3] += by;
        }
    }
    int rl[2][2], rg[2][2];
#pragma unroll
    for (int tm = 0; tm < 2; tm++) {
        rl[tm][0] = warpM * 32 + tm * 16 + lq;
        rl[tm][1] = rl[tm][0] + 8;
        rg[tm][0] = row0 + rl[tm][0];
        rg[tm][1] = row0 + rl[tm][1];
    }

    float* red0 = smem;
    float* red1 = smem + 128;

    if (MODE == 0) {
        float pa[2][2] = {{0,0},{0,0}}, pb[2][2] = {{0,0},{0,0}};
#pragma unroll
        for (int tn = 0; tn < 8; tn++) {
            int col = warpN * 64 + tn * 8 + lr * 2;
            float w0x = aux[col], w0y = aux[col + 1];
            float w1x = aux[128 + col], w1y = aux[128 + col + 1];
#pragma unroll
            for (int tm = 0; tm < 2; tm++) {
#pragma unroll
                for (int h = 0; h < 2; h++) {
                    float vx = acc[tm][tn][h * 2], vy = acc[tm][tn][h * 2 + 1];
                    if (rg[tm][h] < M)
                        *reinterpret_cast<float2*>(g_node_h + (size_t)rg[tm][h] * 128 + col)
                            = make_float2(vx, vy);
                    pa[tm][h] += vx * w0x + vy * w0y;
                    pb[tm][h] += vx * w1x + vy * w1y;
                }
            }
        }
        if (tid < 128) { red0[tid] = 0.f; red1[tid] = 0.f; }
        __syncthreads();
#pragma unroll
        for (int tm = 0; tm < 2; tm++)
#pragma unroll
            for (int h = 0; h < 2; h++) {
#pragma unroll
                for (int o = 1; o <= 2; o <<= 1) {
                    pa[tm][h] += __shfl_xor_sync(0xffffffffu, pa[tm][h], o);
                    pb[tm][h] += __shfl_xor_sync(0xffffffffu, pb[tm][h], o);
                }
                if (lr == 0) {
                    atomicAdd(&red0[rl[tm][h]], pa[tm][h]);
                    atomicAdd(&red1[rl[tm][h]], pb[tm][h]);
                }
            }
        __syncthreads();
        if (tid < 128 && row0 + tid < M) {
            g_a[row0 + tid] = red0[tid];
            g_b[row0 + tid] = red1[tid];
        }
    }
    else if (MODE == 1) {
        int dsts[2][2];
#pragma unroll
        for (int tm = 0; tm < 2; tm++)
#pragma unroll
            for (int h = 0; h < 2; h++)
                dsts[tm][h] = (rg[tm][h] < M) ? dst_idx[rg[tm][h]] : -1;

        float pd[2][2] = {{0,0},{0,0}};
#pragma unroll
        for (int tn = 0; tn < 8; tn++) {
            int col = warpN * 64 + tn * 8 + lr * 2;
            float w2x = aux[col], w2y = aux[col + 1];
#pragma unroll
            for (int tm = 0; tm < 2; tm++) {
#pragma unroll
                for (int h = 0; h < 2; h++) {
                    float vx = acc[tm][tn][h * 2], vy = acc[tm][tn][h * 2 + 1];
                    pd[tm][h] += vx * w2x + vy * w2y;
                    if (dsts[tm][h] >= 0)
                        atomicAdd(reinterpret_cast<float2*>(
                            g_agg_e + (size_t)dsts[tm][h] * 128 + col),
                            make_float2(vx, vy));
                }
            }
        }
        if (tid < 128) red0[tid] = 0.f;
        __syncthreads();
#pragma unroll
        for (int tm = 0; tm < 2; tm++)
#pragma unroll
            for (int h = 0; h < 2; h++) {
#pragma unroll
                for (int o = 1; o <= 2; o <<= 1)
                    pd[tm][h] += __shfl_xor_sync(0xffffffffu, pd[tm][h], o);
                if (lr == 0) atomicAdd(&red0[rl[tm][h]], pd[tm][h]);
            }
        __syncthreads();
        if (tid < 128 && row0 + tid < M)
            g_edot[row0 + tid] = red0[tid];
    }
    else {
        float ps[2][2] = {{0,0},{0,0}}, pq[2][2] = {{0,0},{0,0}};
#pragma unroll
        for (int tn = 0; tn < 8; tn++) {
            int col = warpN * 64 + tn * 8 + lr * 2;
#pragma unroll
            for (int tm = 0; tm < 2; tm++) {
#pragma unroll
                for (int h = 0; h < 2; h++) {
                    float2 res = (rg[tm][h] < M)
                        ? *reinterpret_cast<const float2*>(g_node_h + (size_t)rg[tm][h] * 128 + col)
                        : make_float2(0.f, 0.f);
                    float x0 = acc[tm][tn][h * 2] + res.x;
                    float x1 = acc[tm][tn][h * 2 + 1] + res.y;
                    acc[tm][tn][h * 2] = x0;
                    acc[tm][tn][h * 2 + 1] = x1;
                    ps[tm][h] += x0 + x1;
                    pq[tm][h] += x0 * x0 + x1 * x1;
                }
            }
        }
        if (tid < 128) { red0[tid] = 0.f; red1[tid] = 0.f; }
        __syncthreads();
#pragma unroll
        for (int tm = 0; tm < 2; tm++)
#pragma unroll
            for (int h = 0; h < 2; h++) {
#pragma unroll
                for (int o = 1; o <= 2; o <<= 1) {
                    ps[tm][h] += __shfl_xor_sync(0xffffffffu, ps[tm][h], o);
                    pq[tm][h] += __shfl_xor_sync(0xffffffffu, pq[tm][h], o);
                }
                if (lr == 0) {
                    atomicAdd(&red0[rl[tm][h]], ps[tm][h]);
                    atomicAdd(&red1[rl[tm][h]], pq[tm][h]);
                }
            }
        __syncthreads();
        float mean_[2][2], inv_[2][2];
#pragma unroll
        for (int tm = 0; tm < 2; tm++)
#pragma unroll
            for (int h = 0; h < 2; h++) {
                float m = red0[rl[tm][h]] * (1.f / 128.f);
                float var = red1[rl[tm][h]] * (1.f / 128.f) - m * m;
                mean_[tm][h] = m;
                inv_[tm][h] = rsqrtf(fmaxf(var, 0.f) + 1e-6f);
            }
        float pa[2][2] = {{0,0},{0,0}}, pb[2][2] = {{0,0},{0,0}};
#pragma unroll
        for (int tn = 0; tn < 8; tn++) {
            int col = warpN * 64 + tn * 8 + lr * 2;
            float scx = lns[col], scy = lns[col + 1];
            float bix = lnb[col], biy = lnb[col + 1];
            float w0x = aux[col], w0y = aux[col + 1];
            float w1x = aux[128 + col], w1y = aux[128 + col + 1];
#pragma unroll
            for (int tm = 0; tm < 2; tm++) {
#pragma unroll
                for (int h = 0; h < 2; h++) {
                    float y0 = fmaxf(0.f, (acc[tm][tn][h * 2] - mean_[tm][h]) * inv_[tm][h] * scx + bix);
                    float y1 = fmaxf(0.f, (acc[tm][tn][h * 2 + 1] - mean_[tm][h]) * inv_[tm][h] * scy + biy);
                    if (rg[tm][h] < M)
                        *reinterpret_cast<float2*>(dest + (size_t)rg[tm][h] * 128 + col)
                            = make_float2(y0, y1);
                    pa[tm][h] += y0 * w0x + y1 * w0y;
                    pb[tm][h] += y0 * w1x + y1 * w1y;
                }
            }
        }
        if (doab) {
            __syncthreads();
            if (tid < 128) { red0[tid] = 0.f; red1[tid] = 0.f; }
            __syncthreads();
#pragma unroll
            for (int tm = 0; tm < 2; tm++)
#pragma unroll
                for (int h = 0; h < 2; h++) {
#pragma unroll
                    for (int o = 1; o <= 2; o <<= 1) {
                        pa[tm][h] += __shfl_xor_sync(0xffffffffu, pa[tm][h], o);
                        pb[tm][h] += __shfl_xor_sync(0xffffffffu, pb[tm][h], o);
                    }
                    if (lr == 0) {
                        atomicAdd(&red0[rl[tm][h]], pa[tm][h]);
                        atomicAdd(&red1[rl[tm][h]], pb[tm][h]);
                    }
                }
            __syncthreads();
            if (tid < 128 && row0 + tid < M) {
                g_a[row0 + tid] = red0[tid];
                g_b[row0 + tid] = red1[tid];
            }
        }
    }
}

// ---------------- per-layer edge phase: gate + scatter src_f*wgt ----------------
__global__ void __launch_bounds__(256)
edge_kernel(const int* __restrict__ src_idx, const int* __restrict__ dst_idx,
            const float* __restrict__ b_top, float* __restrict__ w_out)
{
    int e = (blockIdx.x * blockDim.x + threadIdx.x) >> 5;
    int lane = threadIdx.x & 31;
    if (e >= NE) return;

    int s = src_idx[e];
    int d = dst_idx[e];

    float wgt;
    if (lane == 0) {
        float g = g_a[s] + g_b[d] + g_edot[e] + b_top[0];
        wgt = 1.f / (1.f + __expf(-g));
    }
    wgt = __shfl_sync(0xffffffffu, wgt, 0);

    float4 sv = *reinterpret_cast<const float4*>(g_node_h + (size_t)s * 128 + lane * 4);
    float4 msg = make_float4(sv.x * wgt, sv.y * wgt, sv.z * wgt, sv.w * wgt);
    atomicAdd(reinterpret_cast<float4*>(g_agg + (size_t)d * 128 + lane * 4), msg);

    if (w_out != nullptr && lane == 0) w_out[e] = wgt;
}

// ---------------- launch ----------------
extern "C" void kernel_launch(void* const* d_in, const int* in_sizes, int n_in,
                              void* d_out, int out_size)
{
    const float* nf     = (const float*)d_in[0];
    const float* ef     = (const float*)d_in[1];
    const int*   ei     = (const int*)  d_in[2];
    const float* W_node = (const float*)d_in[3];
    const float* b_node = (const float*)d_in[4];
    const float* W_edge = (const float*)d_in[5];
    const float* b_edge = (const float*)d_in[6];
    const float* W_gnn  = (const float*)d_in[7];
    const float* b_gnn  = (const float*)d_in[8];
    const float* W_top  = (const float*)d_in[9];
    const float* b_top  = (const float*)d_in[10];
    const float* ln_s   = (const float*)d_in[11];
    const float* ln_b   = (const float*)d_in[12];

    float* out       = (float*)d_out;
    float* out_nodes = out;
    float* out_w     = out + (size_t)NN * 128;

    const int* src = ei;
    const int* dst = ei + NE;

    const int SMEM_SZ = 2 * 4 * 128 * 80;   // 81920 B
    cudaFuncSetAttribute(mma_gemm_kernel<128, 0>, cudaFuncAttributeMaxDynamicSharedMemorySize, SMEM_SZ);
    cudaFuncSetAttribute(mma_gemm_kernel<64, 1>,  cudaFuncAttributeMaxDynamicSharedMemorySize, SMEM_SZ);
    cudaFuncSetAttribute(mma_gemm_kernel<256, 2>, cudaFuncAttributeMaxDynamicSharedMemorySize, SMEM_SZ);

    __nv_bfloat16 *wthn = nullptr, *wtln = nullptr, *wthe = nullptr, *wtle = nullptr;
    __nv_bfloat16 *wthg = nullptr, *wtlg = nullptr;
    cudaGetSymbolAddress((void**)&wthn, g_wth_node);
    cudaGetSymbolAddress((void**)&wtln, g_wtl_node);
    cudaGetSymbolAddress((void**)&wthe, g_wth_edge);
    cudaGetSymbolAddress((void**)&wtle, g_wtl_edge);
    cudaGetSymbolAddress((void**)&wthg, g_wth_gnn);
    cudaGetSymbolAddress((void**)&wtlg, g_wtl_gnn);
    float* nodeh = nullptr; float* aggep = nullptr;
    cudaGetSymbolAddress((void**)&nodeh, g_node_h);
    cudaGetSymbolAddress((void**)&aggep, g_agg_e);

    zero_buf_kernel<<<1024, 256>>>(aggep, NN * 128 / 4);
    transpose_node_kernel<<<(128 * 128 + 255) / 256, 256>>>(W_node);
    transpose_edge_kernel<<<(64 * 128 + 255) / 256, 256>>>(W_edge);
    transpose_gnn_kernel<<<(3 * 256 * 128 + 255) / 256, 256>>>(W_gnn);

    // node embed (+ a,b dots)
    mma_gemm_kernel<128, 0><<<(NN + 127) / 128, 256, SMEM_SZ>>>(
        nf, wthn, wtln, b_node, NN, W_top, nullptr, nullptr, nullptr, nullptr, 0);
    // edge embed (edot + agg_e; edge_h never materialized)
    mma_gemm_kernel<64, 1><<<(NE + 127) / 128, 256, SMEM_SZ>>>(
        ef, wthe, wtle, b_edge, NE, W_top + 256, dst, nullptr, nullptr, nullptr, 0);

    for (int i = 0; i < 3; i++) {
        copy_agg_kernel<<<1024, 256>>>();
        edge_kernel<<<(NE * 32 + 255) / 256, 256>>>(
            src, dst, b_top, (i == 2) ? out_w : nullptr);
        mma_gemm_kernel<256, 2><<<(NN + 127) / 128, 256, SMEM_SZ>>>(
            nullptr, wthg + (size_t)i * 128 * 256, wtlg + (size_t)i * 128 * 256,
            b_gnn + i * 128, NN,
            W_top, nullptr, ln_s + i * 128, ln_b + i * 128,
            (i == 2) ? out_nodes : nodeh, (i < 2) ? 1 : 0);
    }
}

// round 9
// speedup vs baseline: 1.8715x; 1.0458x over previous
#include <cuda_runtime.h>
#include <cuda_bf16.h>
#include <math.h>
#include <stdint.h>

#define NN 50000
#define NE 200000

// ---------------- scratch (device globals; no allocation) ----------------
__device__ float g_node_h[(size_t)NN * 128];
__device__ float g_agg[(size_t)NN * 128];     // per-layer: agg_e copy + scatter
__device__ float g_agg_e[(size_t)NN * 128];   // layer-invariant: sum of edge_h into dst
__device__ float g_ef_sum[(size_t)NN * 64];   // sum of raw edge features into dst
__device__ float g_indeg[NN];
__device__ float g_a[NN];                     // node_h . w0
__device__ float g_b[NN];                     // node_h . w1
__device__ float g_edot[NE];                  // edge_h . w2 (layer-invariant)
__device__ float g_ve[64];                    // W_edge @ w2
__device__ float g_vc;                        // b_edge . w2
// pre-split bf16 weight planes, [n][k] layout (B operand, col-major)
__device__ __nv_bfloat16 g_wth_node[128 * 128], g_wtl_node[128 * 128];
__device__ __nv_bfloat16 g_wth_edge[128 * 64],  g_wtl_edge[128 * 64];
__device__ __nv_bfloat16 g_wth_gnn[3 * 128 * 256], g_wtl_gnn[3 * 128 * 256];

// ---------------- weight transpose + split ----------------
__device__ __forceinline__ void split_store(float x, __nv_bfloat16* ph, __nv_bfloat16* pl) {
    __nv_bfloat16 h = __float2bfloat16(x);
    *ph = h;
    *pl = __float2bfloat16(x - __bfloat162float(h));
}
__global__ void transpose_node_kernel(const float* __restrict__ W)
{
    int i = blockIdx.x * blockDim.x + threadIdx.x;
    if (i < 128 * 128) {
        int k = i >> 7, n = i & 127;
        split_store(W[i], &g_wth_node[n * 128 + k], &g_wtl_node[n * 128 + k]);
    }
}
__global__ void transpose_edge_kernel(const float* __restrict__ W)
{
    int i = blockIdx.x * blockDim.x + threadIdx.x;
    if (i < 64 * 128) {
        int k = i >> 7, n = i & 127;
        split_store(W[i], &g_wth_edge[n * 64 + k], &g_wtl_edge[n * 64 + k]);
    }
}
__global__ void transpose_gnn_kernel(const float* __restrict__ W)
{
    int i = blockIdx.x * blockDim.x + threadIdx.x;
    if (i < 3 * 256 * 128) {
        int l = i / 32768, r = i % 32768;
        int k = r >> 7, n = r & 127;
        split_store(W[i], &g_wth_gnn[l * 32768 + n * 256 + k],
                          &g_wtl_gnn[l * 32768 + n * 256 + k]);
    }
}

// ---------------- v_e = W_edge @ w2, c = b_edge . w2 ----------------
__global__ void ve_kernel(const float* __restrict__ W_edge,
                          const float* __restrict__ b_edge,
                          const float* __restrict__ W_top)
{
    int k = threadIdx.x;           // 0..63
    float s = 0.f;
    for (int n = 0; n < 128; n++) s += W_edge[k * 128 + n] * W_top[256 + n];
    g_ve[k] = s;
    if (k == 0) {
        float c = 0.f;
        for (int n = 0; n < 128; n++) c += b_edge[n] * W_top[256 + n];
        g_vc = c;
    }
}

// ---------------- edge feature sum + edot (16 lanes per edge) ----------------
__global__ void __launch_bounds__(256)
edge_sum_kernel(const float* __restrict__ ef, const int* __restrict__ dst_idx)
{
    int t = blockIdx.x * blockDim.x + threadIdx.x;
    int e = t >> 4;
    int l = t & 15;
    if (e >= NE) return;

    float4 v  = *reinterpret_cast<const float4*>(ef + (size_t)e * 64 + l * 4);
    float4 ve = *reinterpret_cast<const float4*>(g_ve + l * 4);
    float p = v.x * ve.x + v.y * ve.y + v.z * ve.z + v.w * ve.w;
#pragma unroll
    for (int o = 1; o < 16; o <<= 1) p += __shfl_xor_sync(0xffffffffu, p, o);

    int d = dst_idx[e];
    if (l == 0) {
        g_edot[e] = p + g_vc;
        atomicAdd(&g_indeg[d], 1.f);
    }
    atomicAdd(reinterpret_cast<float4*>(g_ef_sum + (size_t)d * 64 + l * 4), v);
}

// ---------------- zero / copy helpers ----------------
__global__ void zero_buf_kernel(float* __restrict__ p, int n4)
{
    float4 z = make_float4(0.f, 0.f, 0.f, 0.f);
    for (int i = blockIdx.x * blockDim.x + threadIdx.x; i < n4; i += gridDim.x * blockDim.x)
        reinterpret_cast<float4*>(p)[i] = z;
}
__global__ void copy_agg_kernel()   // g_agg = g_agg_e
{
    const int n4 = NN * 128 / 4;
    for (int i = blockIdx.x * blockDim.x + threadIdx.x; i < n4; i += gridDim.x * blockDim.x)
        reinterpret_cast<float4*>(g_agg)[i] = reinterpret_cast<const float4*>(g_agg_e)[i];
}

// ---------------- mma / ldmatrix / cp.async / bf16 helpers ----------------
#define MMA_BF16(d, a0, a1, a2, a3, b0, b1)                                    \
    asm volatile(                                                              \
        "mma.sync.aligned.m16n8k16.row.col.f32.bf16.bf16.f32 "                 \
        "{%0,%1,%2,%3}, {%4,%5,%6,%7}, {%8,%9}, {%0,%1,%2,%3};"                \
        : "+f"((d)[0]), "+f"((d)[1]), "+f"((d)[2]), "+f"((d)[3])               \
        : "r"(a0), "r"(a1), "r"(a2), "r"(a3), "r"(b0), "r"(b1))

#define LDSM_X4(R, addr)                                                       \
    asm volatile("ldmatrix.sync.aligned.m8n8.x4.shared.b16 {%0,%1,%2,%3}, [%4];" \
        : "=r"((R)[0]), "=r"((R)[1]), "=r"((R)[2]), "=r"((R)[3]) : "r"(addr))

#define ST_V2(addr, x, y)                                                      \
    asm volatile("st.shared.v2.u32 [%0], {%1,%2};" :: "r"(addr), "r"(x), "r"(y))

#define CP_ASYNC16(saddr, gptr) \
    asm volatile("cp.async.cg.shared.global [%0], [%1], 16;" :: "r"(saddr), "l"(gptr))
#define CP_COMMIT() asm volatile("cp.async.commit_group;")
#define CP_WAIT0()  asm volatile("cp.async.wait_group 0;")

__device__ __forceinline__ uint32_t bf16x2_split(float2 f, float2& rem) {
    uint32_t h;
    asm("cvt.rn.bf16x2.f32 %0, %1, %2;" : "=r"(h) : "f"(f.y), "f"(f.x));
    float hx = __uint_as_float(h << 16);
    float hy = __uint_as_float(h & 0xFFFF0000u);
    rem.x = f.x - hx;
    rem.y = f.y - hy;
    return h;
}
__device__ __forceinline__ uint32_t bf16x2_pack(float2 f) {
    uint32_t h;
    asm("cvt.rn.bf16x2.f32 %0, %1, %2;" : "=r"(h) : "f"(f.y), "f"(f.x));
    return h;
}

// =====================================================================
// Fused bf16x2-split GEMM.
// MODE 0 (node embed):  write g_node_h; a = y.w0, b = y.w1
// MODE 2 (update):      A = [node_h | g_agg]; x = node_h + (acc+bias);
//                       LayerNorm+ReLU -> dest; opt a,b dots
// MODE 3 (agg_e):       A = ef_sum [NN,64]; out = acc + indeg[r]*bias -> dest
// =====================================================================
template <int KTOT, int MODE>
__global__ void __launch_bounds__(256, 2)
mma_gemm_kernel(const float* __restrict__ A,
                const __nv_bfloat16* __restrict__ WTH,
                const __nv_bfloat16* __restrict__ WTL,
                const float* __restrict__ bias,
                int M,
                const float* __restrict__ aux,    // MODE0/2: W_top; MODE3: indeg
                const float* __restrict__ lns,
                const float* __restrict__ lnb,
                float* __restrict__ dest,
                int doab)
{
    extern __shared__ float smem[];
    constexpr int NCH = KTOT / 32;
    constexpr int PITCH = 80;
    constexpr int PLANE = 128 * PITCH;
    constexpr int OFF_AH = 0, OFF_AL = PLANE, OFF_BH = 2 * PLANE, OFF_BL = 3 * PLANE;
    constexpr int BUF = 4 * PLANE;

    const int tid   = threadIdx.x;
    const int wid   = tid >> 5;
    const int lane  = tid & 31;
    const int warpM = wid >> 1;
    const int warpN = wid & 1;
    const int lq    = lane >> 2;
    const int lr    = lane & 3;
    const int row0  = blockIdx.x * 128;

    const uint32_t sbase = (uint32_t)__cvta_generic_to_shared(smem);

    float acc[2][8][4];
#pragma unroll
    for (int i = 0; i < 2; i++)
#pragma unroll
        for (int j = 0; j < 8; j++)
#pragma unroll
            for (int q = 0; q < 4; q++) acc[i][j][q] = 0.f;

    float4 va[4];
    auto loadA = [&](int kc) {
#pragma unroll
        for (int l = 0; l < 4; l++) {
            int idx = tid + l * 256;
            int r = idx >> 3;
            int kq = (idx & 7) * 4;
            int grow = row0 + r;
            if (grow >= M) grow = M - 1;
            const float* src;
            if (MODE == 2)
                src = (kc < 4) ? g_node_h + (size_t)grow * 128 + kc * 32 + kq
                               : g_agg + (size_t)grow * 128 + (kc - 4) * 32 + kq;
            else
                src = A + (size_t)grow * KTOT + kc * 32 + kq;
            va[l] = *reinterpret_cast<const float4*>(src);
        }
    };
    auto storeA = [&](int buf) {
        const uint32_t bufo = sbase + buf * BUF;
#pragma unroll
        for (int l = 0; l < 4; l++) {
            int idx = tid + l * 256;
            int r = idx >> 3;
            int kq = (idx & 7) * 4;
            uint32_t off = (uint32_t)(r * PITCH + kq * 2);
            float2 rm0, rm1;
            uint32_t h0 = bf16x2_split(make_float2(va[l].x, va[l].y), rm0);
            uint32_t h1 = bf16x2_split(make_float2(va[l].z, va[l].w), rm1);
            ST_V2(bufo + OFF_AH + off, h0, h1);
            ST_V2(bufo + OFF_AL + off, bf16x2_pack(rm0), bf16x2_pack(rm1));
        }
    };
    auto fillB = [&](int kc, int buf) {
        const uint32_t bufo = sbase + buf * BUF;
#pragma unroll
        for (int l = 0; l < 2; l++) {
            int gr = tid + l * 256;
            int row = gr >> 2;
            int seg = gr & 3;
            uint32_t soff = (uint32_t)(row * PITCH + seg * 16);
            const __nv_bfloat16* sh = WTH + (size_t)row * KTOT + kc * 32 + seg * 8;
            const __nv_bfloat16* sl = WTL + (size_t)row * KTOT + kc * 32 + seg * 8;
            CP_ASYNC16(bufo + OFF_BH + soff, sh);
            CP_ASYNC16(bufo + OFF_BL + soff, sl);
        }
        CP_COMMIT();
    };

    loadA(0);
    fillB(0, 0);
    storeA(0);
    CP_WAIT0();
    __syncthreads();

    const int g   = lane & 15;
    const int hh  = lane >> 4;
    const int q8  = lane & 7;
    const int seg = (lane >> 3) & 3;

    for (int kc = 0; kc < NCH; kc++) {
        const int cur = kc & 1;
        if (kc + 1 < NCH) {
            loadA(kc + 1);
            fillB(kc + 1, cur ^ 1);
        }

        const uint32_t bufo = sbase + cur * BUF;
#pragma unroll
        for (int ks = 0; ks < 2; ks++) {
            uint32_t ah[2][4], al[2][4];
#pragma unroll
            for (int tm = 0; tm < 2; tm++) {
                uint32_t ra = bufo + OFF_AH
                    + (uint32_t)((warpM * 32 + tm * 16 + g) * PITCH + ks * 32 + hh * 16);
                LDSM_X4(ah[tm], ra);
                LDSM_X4(al[tm], ra + (OFF_AL - OFF_AH));
            }
#pragma unroll
            for (int p = 0; p < 4; p++) {
                int n = warpN * 64 + (2 * p + (seg >> 1)) * 8 + q8;
                uint32_t rb = bufo + OFF_BH
                    + (uint32_t)(n * PITCH + ks * 32 + (seg & 1) * 16);
                uint32_t bh[4], bl[4];
                LDSM_X4(bh, rb);
                LDSM_X4(bl, rb + (OFF_BL - OFF_BH));
                MMA_BF16(acc[0][2 * p],     ah[0][0], ah[0][1], ah[0][2], ah[0][3], bh[0], bh[1]);
                MMA_BF16(acc[1][2 * p],     ah[1][0], ah[1][1], ah[1][2], ah[1][3], bh[0], bh[1]);
                MMA_BF16(acc[0][2 * p + 1], ah[0][0], ah[0][1], ah[0][2], ah[0][3], bh[2], bh[3]);
                MMA_BF16(acc[1][2 * p + 1], ah[1][0], ah[1][1], ah[1][2], ah[1][3], bh[2], bh[3]);
                MMA_BF16(acc[0][2 * p],     al[0][0], al[0][1], al[0][2], al[0][3], bh[0], bh[1]);
                MMA_BF16(acc[1][2 * p],     al[1][0], al[1][1], al[1][2], al[1][3], bh[0], bh[1]);
                MMA_BF16(acc[0][2 * p + 1], al[0][0], al[0][1], al[0][2], al[0][3], bh[2], bh[3]);
                MMA_BF16(acc[1][2 * p + 1], al[1][0], al[1][1], al[1][2], al[1][3], bh[2], bh[3]);
                MMA_BF16(acc[0][2 * p],     ah[0][0], ah[0][1], ah[0][2], ah[0][3], bl[0], bl[1]);
                MMA_BF16(acc[1][2 * p],     ah[1][0], ah[1][1], ah[1][2], ah[1][3], bl[0], bl[1]);
                MMA_BF16(acc[0][2 * p + 1], ah[0][0], ah[0][1], ah[0][2], ah[0][3], bl[2], bl[3]);
                MMA_BF16(acc[1][2 * p + 1], ah[1][0], ah[1][1], ah[1][2], ah[1][3], bl[2], bl[3]);
            }
        }
        if (kc + 1 < NCH) storeA(cur ^ 1);
        CP_WAIT0();
        __syncthreads();
    }

    // ---------------- epilogue ----------------
    if (MODE != 3) {
#pragma unroll
        for (int tn = 0; tn < 8; tn++) {
            int col = warpN * 64 + tn * 8 + lr * 2;
            float bx = bias[col], by = bias[col + 1];
#pragma unroll
            for (int tm = 0; tm < 2; tm++) {
                acc[tm][tn][0] += bx; acc[tm][tn][1] += by;
                acc[tm][tn][2] += bx; acc[tm][tn][3] += by;
            }
        }
    }
    int rl[2][2], rg[2][2];
#pragma unroll
    for (int tm = 0; tm < 2; tm++) {
        rl[tm][0] = warpM * 32 + tm * 16 + lq;
        rl[tm][1] = rl[tm][0] + 8;
        rg[tm][0] = row0 + rl[tm][0];
        rg[tm][1] = row0 + rl[tm][1];
    }

    float* red0 = smem;
    float* red1 = smem + 128;

    if (MODE == 0) {
        float pa[2][2] = {{0,0},{0,0}}, pb[2][2] = {{0,0},{0,0}};
#pragma unroll
        for (int tn = 0; tn < 8; tn++) {
            int col = warpN * 64 + tn * 8 + lr * 2;
            float w0x = aux[col], w0y = aux[col + 1];
            float w1x = aux[128 + col], w1y = aux[128 + col + 1];
#pragma unroll
            for (int tm = 0; tm < 2; tm++) {
#pragma unroll
                for (int h = 0; h < 2; h++) {
                    float vx = acc[tm][tn][h * 2], vy = acc[tm][tn][h * 2 + 1];
                    if (rg[tm][h] < M)
                        *reinterpret_cast<float2*>(g_node_h + (size_t)rg[tm][h] * 128 + col)
                            = make_float2(vx, vy);
                    pa[tm][h] += vx * w0x + vy * w0y;
                    pb[tm][h] += vx * w1x + vy * w1y;
                }
            }
        }
        if (tid < 128) { red0[tid] = 0.f; red1[tid] = 0.f; }
        __syncthreads();
#pragma unroll
        for (int tm = 0; tm < 2; tm++)
#pragma unroll
            for (int h = 0; h < 2; h++) {
#pragma unroll
                for (int o = 1; o <= 2; o <<= 1) {
                    pa[tm][h] += __shfl_xor_sync(0xffffffffu, pa[tm][h], o);
                    pb[tm][h] += __shfl_xor_sync(0xffffffffu, pb[tm][h], o);
                }
                if (lr == 0) {
                    atomicAdd(&red0[rl[tm][h]], pa[tm][h]);
                    atomicAdd(&red1[rl[tm][h]], pb[tm][h]);
                }
            }
        __syncthreads();
        if (tid < 128 && row0 + tid < M) {
            g_a[row0 + tid] = red0[tid];
            g_b[row0 + tid] = red1[tid];
        }
    }
    else if (MODE == 3) {
        float ind[2][2];
#pragma unroll
        for (int tm = 0; tm < 2; tm++)
#pragma unroll
            for (int h = 0; h < 2; h++)
                ind[tm][h] = (rg[tm][h] < M) ? aux[rg[tm][h]] : 0.f;
#pragma unroll
        for (int tn = 0; tn < 8; tn++) {
            int col = warpN * 64 + tn * 8 + lr * 2;
            float bx = bias[col], by = bias[col + 1];
#pragma unroll
            for (int tm = 0; tm < 2; tm++) {
#pragma unroll
                for (int h = 0; h < 2; h++) {
                    if (rg[tm][h] < M) {
                        float2 v = make_float2(acc[tm][tn][h * 2] + ind[tm][h] * bx,
                                               acc[tm][tn][h * 2 + 1] + ind[tm][h] * by);
                        *reinterpret_cast<float2*>(dest + (size_t)rg[tm][h] * 128 + col) = v;
                    }
                }
            }
        }
    }
    else {
        float ps[2][2] = {{0,0},{0,0}}, pq[2][2] = {{0,0},{0,0}};
#pragma unroll
        for (int tn = 0; tn < 8; tn++) {
            int col = warpN * 64 + tn * 8 + lr * 2;
#pragma unroll
            for (int tm = 0; tm < 2; tm++) {
#pragma unroll
                for (int h = 0; h < 2; h++) {
                    float2 res = (rg[tm][h] < M)
                        ? *reinterpret_cast<const float2*>(g_node_h + (size_t)rg[tm][h] * 128 + col)
                        : make_float2(0.f, 0.f);
                    float x0 = acc[tm][tn][h * 2] + res.x;
                    float x1 = acc[tm][tn][h * 2 + 1] + res.y;
                    acc[tm][tn][h * 2] = x0;
                    acc[tm][tn][h * 2 + 1] = x1;
                    ps[tm][h] += x0 + x1;
                    pq[tm][h] += x0 * x0 + x1 * x1;
                }
            }
        }
        if (tid < 128) { red0[tid] = 0.f; red1[tid] = 0.f; }
        __syncthreads();
#pragma unroll
        for (int tm = 0; tm < 2; tm++)
#pragma unroll
            for (int h = 0; h < 2; h++) {
#pragma unroll
                for (int o = 1; o <= 2; o <<= 1) {
                    ps[tm][h] += __shfl_xor_sync(0xffffffffu, ps[tm][h], o);
                    pq[tm][h] += __shfl_xor_sync(0xffffffffu, pq[tm][h], o);
                }
                if (lr == 0) {
                    atomicAdd(&red0[rl[tm][h]], ps[tm][h]);
                    atomicAdd(&red1[rl[tm][h]], pq[tm][h]);
                }
            }
        __syncthreads();
        float mean_[2][2], inv_[2][2];
#pragma unroll
        for (int tm = 0; tm < 2; tm++)
#pragma unroll
            for (int h = 0; h < 2; h++) {
                float m = red0[rl[tm][h]] * (1.f / 128.f);
                float var = red1[rl[tm][h]] * (1.f / 128.f) - m * m;
                mean_[tm][h] = m;
                inv_[tm][h] = rsqrtf(fmaxf(var, 0.f) + 1e-6f);
            }
        float pa[2][2] = {{0,0},{0,0}}, pb[2][2] = {{0,0},{0,0}};
#pragma unroll
        for (int tn = 0; tn < 8; tn++) {
            int col = warpN * 64 + tn * 8 + lr * 2;
            float scx = lns[col], scy = lns[col + 1];
            float bix = lnb[col], biy = lnb[col + 1];
            float w0x = aux[col], w0y = aux[col + 1];
            float w1x = aux[128 + col], w1y = aux[128 + col + 1];
#pragma unroll
            for (int tm = 0; tm < 2; tm++) {
#pragma unroll
                for (int h = 0; h < 2; h++) {
                    float y0 = fmaxf(0.f, (acc[tm][tn][h * 2] - mean_[tm][h]) * inv_[tm][h] * scx + bix);
                    float y1 = fmaxf(0.f, (acc[tm][tn][h * 2 + 1] - mean_[tm][h]) * inv_[tm][h] * scy + biy);
                    if (rg[tm][h] < M)
                        *reinterpret_cast<float2*>(dest + (size_t)rg[tm][h] * 128 + col)
                            = make_float2(y0, y1);
                    pa[tm][h] += y0 * w0x + y1 * w0y;
                    pb[tm][h] += y0 * w1x + y1 * w1y;
                }
            }
        }
        if (doab) {
            __syncthreads();
            if (tid < 128) { red0[tid] = 0.f; red1[tid] = 0.f; }
            __syncthreads();
#pragma unroll
            for (int tm = 0; tm < 2; tm++)
#pragma unroll
                for (int h = 0; h < 2; h++) {
#pragma unroll
                    for (int o = 1; o <= 2; o <<= 1) {
                        pa[tm][h] += __shfl_xor_sync(0xffffffffu, pa[tm][h], o);
                        pb[tm][h] += __shfl_xor_sync(0xffffffffu, pb[tm][h], o);
                    }
                    if (lr == 0) {
                        atomicAdd(&red0[rl[tm][h]], pa[tm][h]);
                        atomicAdd(&red1[rl[tm][h]], pb[tm][h]);
                    }
                }
            __syncthreads();
            if (tid < 128 && row0 + tid < M) {
                g_a[row0 + tid] = red0[tid];
                g_b[row0 + tid] = red1[tid];
            }
        }
    }
}

// ---------------- per-layer edge phase: gate + scatter src_f*wgt ----------------
__global__ void __launch_bounds__(256)
edge_kernel(const int* __restrict__ src_idx, const int* __restrict__ dst_idx,
            const float* __restrict__ b_top, float* __restrict__ w_out)
{
    int e = (blockIdx.x * blockDim.x + threadIdx.x) >> 5;
    int lane = threadIdx.x & 31;
    if (e >= NE) return;

    int s = src_idx[e];
    int d = dst_idx[e];

    float wgt;
    if (lane == 0) {
        float g = g_a[s] + g_b[d] + g_edot[e] + b_top[0];
        wgt = 1.f / (1.f + __expf(-g));
    }
    wgt = __shfl_sync(0xffffffffu, wgt, 0);

    float4 sv = *reinterpret_cast<const float4*>(g_node_h + (size_t)s * 128 + lane * 4);
    float4 msg = make_float4(sv.x * wgt, sv.y * wgt, sv.z * wgt, sv.w * wgt);
    atomicAdd(reinterpret_cast<float4*>(g_agg + (size_t)d * 128 + lane * 4), msg);

    if (w_out != nullptr && lane == 0) w_out[e] = wgt;
}

// ---------------- launch ----------------
extern "C" void kernel_launch(void* const* d_in, const int* in_sizes, int n_in,
                              void* d_out, int out_size)
{
    const float* nf     = (const float*)d_in[0];
    const float* ef     = (const float*)d_in[1];
    const int*   ei     = (const int*)  d_in[2];
    const float* W_node = (const float*)d_in[3];
    const float* b_node = (const float*)d_in[4];
    const float* W_edge = (const float*)d_in[5];
    const float* b_edge = (const float*)d_in[6];
    const float* W_gnn  = (const float*)d_in[7];
    const float* b_gnn  = (const float*)d_in[8];
    const float* W_top  = (const float*)d_in[9];
    const float* b_top  = (const float*)d_in[10];
    const float* ln_s   = (const float*)d_in[11];
    const float* ln_b   = (const float*)d_in[12];

    float* out       = (float*)d_out;
    float* out_nodes = out;
    float* out_w     = out + (size_t)NN * 128;

    const int* src = ei;
    const int* dst = ei + NE;

    const int SMEM_SZ = 2 * 4 * 128 * 80;   // 81920 B
    cudaFuncSetAttribute(mma_gemm_kernel<128, 0>, cudaFuncAttributeMaxDynamicSharedMemorySize, SMEM_SZ);
    cudaFuncSetAttribute(mma_gemm_kernel<64, 3>,  cudaFuncAttributeMaxDynamicSharedMemorySize, SMEM_SZ);
    cudaFuncSetAttribute(mma_gemm_kernel<256, 2>, cudaFuncAttributeMaxDynamicSharedMemorySize, SMEM_SZ);

    __nv_bfloat16 *wthn = nullptr, *wtln = nullptr, *wthe = nullptr, *wtle = nullptr;
    __nv_bfloat16 *wthg = nullptr, *wtlg = nullptr;
    cudaGetSymbolAddress((void**)&wthn, g_wth_node);
    cudaGetSymbolAddress((void**)&wtln, g_wtl_node);
    cudaGetSymbolAddress((void**)&wthe, g_wth_edge);
    cudaGetSymbolAddress((void**)&wtle, g_wtl_edge);
    cudaGetSymbolAddress((void**)&wthg, g_wth_gnn);
    cudaGetSymbolAddress((void**)&wtlg, g_wtl_gnn);
    float* nodeh = nullptr; float* aggep = nullptr;
    float* efsum = nullptr; float* indeg = nullptr;
    cudaGetSymbolAddress((void**)&nodeh, g_node_h);
    cudaGetSymbolAddress((void**)&aggep, g_agg_e);
    cudaGetSymbolAddress((void**)&efsum, g_ef_sum);
    cudaGetSymbolAddress((void**)&indeg, g_indeg);

    // pre-phase: zero accumulators, transposes, v_e
    zero_buf_kernel<<<512, 256>>>(efsum, NN * 64 / 4);
    zero_buf_kernel<<<64, 256>>>(indeg, NN / 4);
    transpose_node_kernel<<<(128 * 128 + 255) / 256, 256>>>(W_node);
    transpose_edge_kernel<<<(64 * 128 + 255) / 256, 256>>>(W_edge);
    transpose_gnn_kernel<<<(3 * 256 * 128 + 255) / 256, 256>>>(W_gnn);
    ve_kernel<<<1, 64>>>(W_edge, b_edge, W_top);

    // edge feature sum + edot (replaces the 200000-row edge GEMM)
    edge_sum_kernel<<<(NE * 16 + 255) / 256, 256>>>(ef, dst);

    // node embed (+ a,b dots)
    mma_gemm_kernel<128, 0><<<(NN + 127) / 128, 256, SMEM_SZ>>>(
        nf, wthn, wtln, b_node, NN, W_top, nullptr, nullptr, nullptr, 0);
    // agg_e = ef_sum @ W_edge + indeg * b_edge  (tiny GEMM)
    mma_gemm_kernel<64, 3><<<(NN + 127) / 128, 256, SMEM_SZ>>>(
        efsum, wthe, wtle, b_edge, NN, indeg, nullptr, nullptr, aggep, 0);

    for (int i = 0; i < 3; i++) {
        copy_agg_kernel<<<1024, 256>>>();
        edge_kernel<<<(NE * 32 + 255) / 256, 256>>>(
            src, dst, b_top, (i == 2) ? out_w : nullptr);
        mma_gemm_kernel<256, 2><<<(NN + 127) / 128, 256, SMEM_SZ>>>(
            nullptr, wthg + (size_t)i * 128 * 256, wtlg + (size_t)i * 128 * 256,
            b_gnn + i * 128, NN,
            W_top, ln_s + i * 128, ln_b + i * 128,
            (i == 2) ? out_nodes : nodeh, (i < 2) ? 1 : 0);
    }
}

// round 11
// speedup vs baseline: 1.9093x; 1.0202x over previous
#include <cuda_runtime.h>
#include <cuda_bf16.h>
#include <math.h>
#include <stdint.h>

#define NN 50000
#define NE 200000

// ---------------- scratch (device globals; no allocation) ----------------
__device__ float g_node_h[(size_t)NN * 128];
__device__ float g_agg[(size_t)NN * 128];     // per-layer scatter target (zeroed)
__device__ float g_agg_e[(size_t)NN * 128];   // layer-invariant: sum of edge_h into dst
__device__ float g_ef_sum[(size_t)NN * 64];   // sum of raw edge features into dst
__device__ float g_indeg[NN];
__device__ float g_a[NN];                     // node_h . w0
__device__ float g_b[NN];                     // node_h . w1
__device__ float g_edot[NE];                  // edge_h . w2 (layer-invariant)
__device__ float g_ve[64];                    // W_edge @ w2
__device__ float g_vc;                        // b_edge . w2
// pre-split bf16 weight planes, [n][k] layout (B operand, col-major)
__device__ __nv_bfloat16 g_wth_node[128 * 128], g_wtl_node[128 * 128];
__device__ __nv_bfloat16 g_wth_edge[128 * 64],  g_wtl_edge[128 * 64];
__device__ __nv_bfloat16 g_wth_gnn[3 * 128 * 256], g_wtl_gnn[3 * 128 * 256];

__device__ __forceinline__ void split_store(float x, __nv_bfloat16* ph, __nv_bfloat16* pl) {
    __nv_bfloat16 h = __float2bfloat16(x);
    *ph = h;
    *pl = __float2bfloat16(x - __bfloat162float(h));
}

// ---------------- fused prologue: zeros + transposes + ve ----------------
// flat index space (note: g_ef_sum = NN*64 floats = 800000 float4!):
//  [0, 800000)          zero g_ef_sum (float4)
//  [800000, 812500)     zero g_indeg (float4)
//  [812500, 828884)     transpose+split W_node (16384)
//  [828884, 837076)     transpose+split W_edge (8192)
//  [837076, 935380)     transpose+split W_gnn (98304)
//  [935380, 935444)     ve (64)
#define PREP_TOTAL 935444
__global__ void prep_kernel(const float* __restrict__ W_node,
                            const float* __restrict__ W_edge,
                            const float* __restrict__ W_gnn,
                            const float* __restrict__ b_edge,
                            const float* __restrict__ W_top)
{
    int i = blockIdx.x * blockDim.x + threadIdx.x;
    if (i < 800000) {
        reinterpret_cast<float4*>(g_ef_sum)[i] = make_float4(0.f, 0.f, 0.f, 0.f);
    } else if (i < 812500) {
        reinterpret_cast<float4*>(g_indeg)[i - 800000] = make_float4(0.f, 0.f, 0.f, 0.f);
    } else if (i < 828884) {
        int j = i - 812500;
        int k = j >> 7, n = j & 127;
        split_store(W_node[j], &g_wth_node[n * 128 + k], &g_wtl_node[n * 128 + k]);
    } else if (i < 837076) {
        int j = i - 828884;
        int k = j >> 7, n = j & 127;
        split_store(W_edge[j], &g_wth_edge[n * 64 + k], &g_wtl_edge[n * 64 + k]);
    } else if (i < 935380) {
        int j = i - 837076;
        int l = j / 32768, r = j % 32768;
        int k = r >> 7, n = r & 127;
        split_store(W_gnn[j], &g_wth_gnn[l * 32768 + n * 256 + k],
                              &g_wtl_gnn[l * 32768 + n * 256 + k]);
    } else if (i < 935444) {
        int k = i - 935380;
        float s = 0.f;
        for (int n = 0; n < 128; n++) s += W_edge[k * 128 + n] * W_top[256 + n];
        g_ve[k] = s;
        if (k == 0) {
            float c = 0.f;
            for (int n = 0; n < 128; n++) c += b_edge[n] * W_top[256 + n];
            g_vc = c;
        }
    }
}

// ---------------- edge feature sum + edot (16 lanes per edge) ----------------
__global__ void __launch_bounds__(256)
edge_sum_kernel(const float* __restrict__ ef, const int* __restrict__ dst_idx)
{
    int t = blockIdx.x * blockDim.x + threadIdx.x;
    int e = t >> 4;
    int l = t & 15;
    if (e >= NE) return;

    float4 v  = *reinterpret_cast<const float4*>(ef + (size_t)e * 64 + l * 4);
    float4 ve = *reinterpret_cast<const float4*>(g_ve + l * 4);
    float p = v.x * ve.x + v.y * ve.y + v.z * ve.z + v.w * ve.w;
#pragma unroll
    for (int o = 1; o < 16; o <<= 1) p += __shfl_xor_sync(0xffffffffu, p, o);

    int d = dst_idx[e];
    if (l == 0) {
        g_edot[e] = p + g_vc;
        atomicAdd(&g_indeg[d], 1.f);
    }
    atomicAdd(reinterpret_cast<float4*>(g_ef_sum + (size_t)d * 64 + l * 4), v);
}

// ---------------- zero helper ----------------
__global__ void zero_buf_kernel(float* __restrict__ p, int n4)
{
    float4 z = make_float4(0.f, 0.f, 0.f, 0.f);
    for (int i = blockIdx.x * blockDim.x + threadIdx.x; i < n4; i += gridDim.x * blockDim.x)
        reinterpret_cast<float4*>(p)[i] = z;
}

// ---------------- mma / ldmatrix / cp.async / bf16 helpers ----------------
#define MMA_BF16(d, a0, a1, a2, a3, b0, b1)                                    \
    asm volatile(                                                              \
        "mma.sync.aligned.m16n8k16.row.col.f32.bf16.bf16.f32 "                 \
        "{%0,%1,%2,%3}, {%4,%5,%6,%7}, {%8,%9}, {%0,%1,%2,%3};"                \
        : "+f"((d)[0]), "+f"((d)[1]), "+f"((d)[2]), "+f"((d)[3])               \
        : "r"(a0), "r"(a1), "r"(a2), "r"(a3), "r"(b0), "r"(b1))

#define LDSM_X4(R, addr)                                                       \
    asm volatile("ldmatrix.sync.aligned.m8n8.x4.shared.b16 {%0,%1,%2,%3}, [%4];" \
        : "=r"((R)[0]), "=r"((R)[1]), "=r"((R)[2]), "=r"((R)[3]) : "r"(addr))

#define ST_V2(addr, x, y)                                                      \
    asm volatile("st.shared.v2.u32 [%0], {%1,%2};" :: "r"(addr), "r"(x), "r"(y))

#define CP_ASYNC16(saddr, gptr) \
    asm volatile("cp.async.cg.shared.global [%0], [%1], 16;" :: "r"(saddr), "l"(gptr))
#define CP_COMMIT() asm volatile("cp.async.commit_group;")
#define CP_WAIT0()  asm volatile("cp.async.wait_group 0;")

__device__ __forceinline__ uint32_t bf16x2_split(float2 f, float2& rem) {
    uint32_t h;
    asm("cvt.rn.bf16x2.f32 %0, %1, %2;" : "=r"(h) : "f"(f.y), "f"(f.x));
    float hx = __uint_as_float(h << 16);
    float hy = __uint_as_float(h & 0xFFFF0000u);
    rem.x = f.x - hx;
    rem.y = f.y - hy;
    return h;
}
__device__ __forceinline__ uint32_t bf16x2_pack(float2 f) {
    uint32_t h;
    asm("cvt.rn.bf16x2.f32 %0, %1, %2;" : "=r"(h) : "f"(f.y), "f"(f.x));
    return h;
}

// =====================================================================
// Fused bf16x2-split GEMM.
// MODE 0 (node embed):  write g_node_h; a = y.w0, b = y.w1
// MODE 2 (update):      A = [node_h | g_agg + g_agg_e]; x = node_h + (acc+bias);
//                       LayerNorm+ReLU -> dest; opt a,b dots
// MODE 3 (agg_e):       A = ef_sum [NN,64]; out = acc + indeg[r]*bias -> dest
// =====================================================================
template <int KTOT, int MODE>
__global__ void __launch_bounds__(256, 2)
mma_gemm_kernel(const float* __restrict__ A,
                const __nv_bfloat16* __restrict__ WTH,
                const __nv_bfloat16* __restrict__ WTL,
                const float* __restrict__ bias,
                int M,
                const float* __restrict__ aux,    // MODE0/2: W_top; MODE3: indeg
                const float* __restrict__ lns,
                const float* __restrict__ lnb,
                float* __restrict__ dest,
                int doab)
{
    extern __shared__ float smem[];
    constexpr int NCH = KTOT / 32;
    constexpr int PITCH = 80;
    constexpr int PLANE = 128 * PITCH;
    constexpr int OFF_AH = 0, OFF_AL = PLANE, OFF_BH = 2 * PLANE, OFF_BL = 3 * PLANE;
    constexpr int BUF = 4 * PLANE;

    const int tid   = threadIdx.x;
    const int wid   = tid >> 5;
    const int lane  = tid & 31;
    const int warpM = wid >> 1;
    const int warpN = wid & 1;
    const int lq    = lane >> 2;
    const int lr    = lane & 3;
    const int row0  = blockIdx.x * 128;

    const uint32_t sbase = (uint32_t)__cvta_generic_to_shared(smem);

    float acc[2][8][4];
#pragma unroll
    for (int i = 0; i < 2; i++)
#pragma unroll
        for (int j = 0; j < 8; j++)
#pragma unroll
            for (int q = 0; q < 4; q++) acc[i][j][q] = 0.f;

    float4 va[4];
    auto loadA = [&](int kc) {
#pragma unroll
        for (int l = 0; l < 4; l++) {
            int idx = tid + l * 256;
            int r = idx >> 3;
            int kq = (idx & 7) * 4;
            int grow = row0 + r;
            if (grow >= M) grow = M - 1;
            if (MODE == 2) {
                if (kc < 4) {
                    va[l] = *reinterpret_cast<const float4*>(
                        g_node_h + (size_t)grow * 128 + kc * 32 + kq);
                } else {
                    float4 x = *reinterpret_cast<const float4*>(
                        g_agg + (size_t)grow * 128 + (kc - 4) * 32 + kq);
                    float4 y = *reinterpret_cast<const float4*>(
                        g_agg_e + (size_t)grow * 128 + (kc - 4) * 32 + kq);
                    va[l] = make_float4(x.x + y.x, x.y + y.y, x.z + y.z, x.w + y.w);
                }
            } else {
                va[l] = *reinterpret_cast<const float4*>(
                    A + (size_t)grow * KTOT + kc * 32 + kq);
            }
        }
    };
    auto storeA = [&](int buf) {
        const uint32_t bufo = sbase + buf * BUF;
#pragma unroll
        for (int l = 0; l < 4; l++) {
            int idx = tid + l * 256;
            int r = idx >> 3;
            int kq = (idx & 7) * 4;
            uint32_t off = (uint32_t)(r * PITCH + kq * 2);
            float2 rm0, rm1;
            uint32_t h0 = bf16x2_split(make_float2(va[l].x, va[l].y), rm0);
            uint32_t h1 = bf16x2_split(make_float2(va[l].z, va[l].w), rm1);
            ST_V2(bufo + OFF_AH + off, h0, h1);
            ST_V2(bufo + OFF_AL + off, bf16x2_pack(rm0), bf16x2_pack(rm1));
        }
    };
    auto fillB = [&](int kc, int buf) {
        const uint32_t bufo = sbase + buf * BUF;
#pragma unroll
        for (int l = 0; l < 2; l++) {
            int gr = tid + l * 256;
            int row = gr >> 2;
            int seg = gr & 3;
            uint32_t soff = (uint32_t)(row * PITCH + seg * 16);
            const __nv_bfloat16* sh = WTH + (size_t)row * KTOT + kc * 32 + seg * 8;
            const __nv_bfloat16* sl = WTL + (size_t)row * KTOT + kc * 32 + seg * 8;
            CP_ASYNC16(bufo + OFF_BH + soff, sh);
            CP_ASYNC16(bufo + OFF_BL + soff, sl);
        }
        CP_COMMIT();
    };

    loadA(0);
    fillB(0, 0);
    storeA(0);
    CP_WAIT0();
    __syncthreads();

    const int g   = lane & 15;
    const int hh  = lane >> 4;
    const int q8  = lane & 7;
    const int seg = (lane >> 3) & 3;

    for (int kc = 0; kc < NCH; kc++) {
        const int cur = kc & 1;
        if (kc + 1 < NCH) {
            loadA(kc + 1);
            fillB(kc + 1, cur ^ 1);
        }

        const uint32_t bufo = sbase + cur * BUF;
#pragma unroll
        for (int ks = 0; ks < 2; ks++) {
            uint32_t ah[2][4], al[2][4];
#pragma unroll
            for (int tm = 0; tm < 2; tm++) {
                uint32_t ra = bufo + OFF_AH
                    + (uint32_t)((warpM * 32 + tm * 16 + g) * PITCH + ks * 32 + hh * 16);
                LDSM_X4(ah[tm], ra);
                LDSM_X4(al[tm], ra + (OFF_AL - OFF_AH));
            }
#pragma unroll
            for (int p = 0; p < 4; p++) {
                int n = warpN * 64 + (2 * p + (seg >> 1)) * 8 + q8;
                uint32_t rb = bufo + OFF_BH
                    + (uint32_t)(n * PITCH + ks * 32 + (seg & 1) * 16);
                uint32_t bh[4], bl[4];
                LDSM_X4(bh, rb);
                LDSM_X4(bl, rb + (OFF_BL - OFF_BH));
                MMA_BF16(acc[0][2 * p],     ah[0][0], ah[0][1], ah[0][2], ah[0][3], bh[0], bh[1]);
                MMA_BF16(acc[1][2 * p],     ah[1][0], ah[1][1], ah[1][2], ah[1][3], bh[0], bh[1]);
                MMA_BF16(acc[0][2 * p + 1], ah[0][0], ah[0][1], ah[0][2], ah[0][3], bh[2], bh[3]);
                MMA_BF16(acc[1][2 * p + 1], ah[1][0], ah[1][1], ah[1][2], ah[1][3], bh[2], bh[3]);
                MMA_BF16(acc[0][2 * p],     al[0][0], al[0][1], al[0][2], al[0][3], bh[0], bh[1]);
                MMA_BF16(acc[1][2 * p],     al[1][0], al[1][1], al[1][2], al[1][3], bh[0], bh[1]);
                MMA_BF16(acc[0][2 * p + 1], al[0][0], al[0][1], al[0][2], al[0][3], bh[2], bh[3]);
                MMA_BF16(acc[1][2 * p + 1], al[1][0], al[1][1], al[1][2], al[1][3], bh[2], bh[3]);
                MMA_BF16(acc[0][2 * p],     ah[0][0], ah[0][1], ah[0][2], ah[0][3], bl[0], bl[1]);
                MMA_BF16(acc[1][2 * p],     ah[1][0], ah[1][1], ah[1][2], ah[1][3], bl[0], bl[1]);
                MMA_BF16(acc[0][2 * p + 1], ah[0][0], ah[0][1], ah[0][2], ah[0][3], bl[2], bl[3]);
                MMA_BF16(acc[1][2 * p + 1], ah[1][0], ah[1][1], ah[1][2], ah[1][3], bl[2], bl[3]);
            }
        }
        if (kc + 1 < NCH) storeA(cur ^ 1);
        CP_WAIT0();
        __syncthreads();
    }

    // ---------------- epilogue ----------------
    if (MODE != 3) {
#pragma unroll
        for (int tn = 0; tn < 8; tn++) {
            int col = warpN * 64 + tn * 8 + lr * 2;
            float bx = bias[col], by = bias[col + 1];
#pragma unroll
            for (int tm = 0; tm < 2; tm++) {
                acc[tm][tn][0] += bx; acc[tm][tn][1] += by;
                acc[tm][tn][2] += bx; acc[tm][tn][3] += by;
            }
        }
    }
    int rl[2][2], rg[2][2];
#pragma unroll
    for (int tm = 0; tm < 2; tm++) {
        rl[tm][0] = warpM * 32 + tm * 16 + lq;
        rl[tm][1] = rl[tm][0] + 8;
        rg[tm][0] = row0 + rl[tm][0];
        rg[tm][1] = row0 + rl[tm][1];
    }

    float* red0 = smem;
    float* red1 = smem + 128;

    if (MODE == 0) {
        float pa[2][2] = {{0,0},{0,0}}, pb[2][2] = {{0,0},{0,0}};
#pragma unroll
        for (int tn = 0; tn < 8; tn++) {
            int col = warpN * 64 + tn * 8 + lr * 2;
            float w0x = aux[col], w0y = aux[col + 1];
            float w1x = aux[128 + col], w1y = aux[128 + col + 1];
#pragma unroll
            for (int tm = 0; tm < 2; tm++) {
#pragma unroll
                for (int h = 0; h < 2; h++) {
                    float vx = acc[tm][tn][h * 2], vy = acc[tm][tn][h * 2 + 1];
                    if (rg[tm][h] < M)
                        *reinterpret_cast<float2*>(g_node_h + (size_t)rg[tm][h] * 128 + col)
                            = make_float2(vx, vy);
                    pa[tm][h] += vx * w0x + vy * w0y;
                    pb[tm][h] += vx * w1x + vy * w1y;
                }
            }
        }
        if (tid < 128) { red0[tid] = 0.f; red1[tid] = 0.f; }
        __syncthreads();
#pragma unroll
        for (int tm = 0; tm < 2; tm++)
#pragma unroll
            for (int h = 0; h < 2; h++) {
#pragma unroll
                for (int o = 1; o <= 2; o <<= 1) {
                    pa[tm][h] += __shfl_xor_sync(0xffffffffu, pa[tm][h], o);
                    pb[tm][h] += __shfl_xor_sync(0xffffffffu, pb[tm][h], o);
                }
                if (lr == 0) {
                    atomicAdd(&red0[rl[tm][h]], pa[tm][h]);
                    atomicAdd(&red1[rl[tm][h]], pb[tm][h]);
                }
            }
        __syncthreads();
        if (tid < 128 && row0 + tid < M) {
            g_a[row0 + tid] = red0[tid];
            g_b[row0 + tid] = red1[tid];
        }
    }
    else if (MODE == 3) {
        float ind[2][2];
#pragma unroll
        for (int tm = 0; tm < 2; tm++)
#pragma unroll
            for (int h = 0; h < 2; h++)
                ind[tm][h] = (rg[tm][h] < M) ? aux[rg[tm][h]] : 0.f;
#pragma unroll
        for (int tn = 0; tn < 8; tn++) {
            int col = warpN * 64 + tn * 8 + lr * 2;
            float bx = bias[col], by = bias[col + 1];
#pragma unroll
            for (int tm = 0; tm < 2; tm++) {
#pragma unroll
                for (int h = 0; h < 2; h++) {
                    if (rg[tm][h] < M) {
                        float2 v = make_float2(acc[tm][tn][h * 2] + ind[tm][h] * bx,
                                               acc[tm][tn][h * 2 + 1] + ind[tm][h] * by);
                        *reinterpret_cast<float2*>(dest + (size_t)rg[tm][h] * 128 + col) = v;
                    }
                }
            }
        }
    }
    else {
        float ps[2][2] = {{0,0},{0,0}}, pq[2][2] = {{0,0},{0,0}};
#pragma unroll
        for (int tn = 0; tn < 8; tn++) {
            int col = warpN * 64 + tn * 8 + lr * 2;
#pragma unroll
            for (int tm = 0; tm < 2; tm++) {
#pragma unroll
                for (int h = 0; h < 2; h++) {
                    float2 res = (rg[tm][h] < M)
                        ? *reinterpret_cast<const float2*>(g_node_h + (size_t)rg[tm][h] * 128 + col)
                        : make_float2(0.f, 0.f);
                    float x0 = acc[tm][tn][h * 2] + res.x;
                    float x1 = acc[tm][tn][h * 2 + 1] + res.y;
                    acc[tm][tn][h * 2] = x0;
                    acc[tm][tn][h * 2 + 1] = x1;
                    ps[tm][h] += x0 + x1;
                    pq[tm][h] += x0 * x0 + x1 * x1;
                }
            }
        }
        if (tid < 128) { red0[tid] = 0.f; red1[tid] = 0.f; }
        __syncthreads();
#pragma unroll
        for (int tm = 0; tm < 2; tm++)
#pragma unroll
            for (int h = 0; h < 2; h++) {
#pragma unroll
                for (int o = 1; o <= 2; o <<= 1) {
                    ps[tm][h] += __shfl_xor_sync(0xffffffffu, ps[tm][h], o);
                    pq[tm][h] += __shfl_xor_sync(0xffffffffu, pq[tm][h], o);
                }
                if (lr == 0) {
                    atomicAdd(&red0[rl[tm][h]], ps[tm][h]);
                    atomicAdd(&red1[rl[tm][h]], pq[tm][h]);
                }
            }
        __syncthreads();
        float mean_[2][2], inv_[2][2];
#pragma unroll
        for (int tm = 0; tm < 2; tm++)
#pragma unroll
            for (int h = 0; h < 2; h++) {
                float m = red0[rl[tm][h]] * (1.f / 128.f);
                float var = red1[rl[tm][h]] * (1.f / 128.f) - m * m;
                mean_[tm][h] = m;
                inv_[tm][h] = rsqrtf(fmaxf(var, 0.f) + 1e-6f);
            }
        float pa[2][2] = {{0,0},{0,0}}, pb[2][2] = {{0,0},{0,0}};
#pragma unroll
        for (int tn = 0; tn < 8; tn++) {
            int col = warpN * 64 + tn * 8 + lr * 2;
            float scx = lns[col], scy = lns[col + 1];
            float bix = lnb[col], biy = lnb[col + 1];
            float w0x = aux[col], w0y = aux[col + 1];
            float w1x = aux[128 + col], w1y = aux[128 + col + 1];
#pragma unroll
            for (int tm = 0; tm < 2; tm++) {
#pragma unroll
                for (int h = 0; h < 2; h++) {
                    float y0 = fmaxf(0.f, (acc[tm][tn][h * 2] - mean_[tm][h]) * inv_[tm][h] * scx + bix);
                    float y1 = fmaxf(0.f, (acc[tm][tn][h * 2 + 1] - mean_[tm][h]) * inv_[tm][h] * scy + biy);
                    if (rg[tm][h] < M)
                        *reinterpret_cast<float2*>(dest + (size_t)rg[tm][h] * 128 + col)
                            = make_float2(y0, y1);
                    pa[tm][h] += y0 * w0x + y1 * w0y;
                    pb[tm][h] += y0 * w1x + y1 * w1y;
                }
            }
        }
        if (doab) {
            __syncthreads();
            if (tid < 128) { red0[tid] = 0.f; red1[tid] = 0.f; }
            __syncthreads();
#pragma unroll
            for (int tm = 0; tm < 2; tm++)
#pragma unroll
                for (int h = 0; h < 2; h++) {
#pragma unroll
                    for (int o = 1; o <= 2; o <<= 1) {
                        pa[tm][h] += __shfl_xor_sync(0xffffffffu, pa[tm][h], o);
                        pb[tm][h] += __shfl_xor_sync(0xffffffffu, pb[tm][h], o);
                    }
                    if (lr == 0) {
                        atomicAdd(&red0[rl[tm][h]], pa[tm][h]);
                        atomicAdd(&red1[rl[tm][h]], pb[tm][h]);
                    }
                }
            __syncthreads();
            if (tid < 128 && row0 + tid < M) {
                g_a[row0 + tid] = red0[tid];
                g_b[row0 + tid] = red1[tid];
            }
        }
    }
}

// ---------------- per-layer edge phase: gate + scatter src_f*wgt ----------------
__global__ void __launch_bounds__(256)
edge_kernel(const int* __restrict__ src_idx, const int* __restrict__ dst_idx,
            const float* __restrict__ b_top, float* __restrict__ w_out)
{
    int e = (blockIdx.x * blockDim.x + threadIdx.x) >> 5;
    int lane = threadIdx.x & 31;
    if (e >= NE) return;

    int s = src_idx[e];
    int d = dst_idx[e];

    float wgt;
    if (lane == 0) {
        float g = g_a[s] + g_b[d] + g_edot[e] + b_top[0];
        wgt = 1.f / (1.f + __expf(-g));
    }
    wgt = __shfl_sync(0xffffffffu, wgt, 0);

    float4 sv = *reinterpret_cast<const float4*>(g_node_h + (size_t)s * 128 + lane * 4);
    float4 msg = make_float4(sv.x * wgt, sv.y * wgt, sv.z * wgt, sv.w * wgt);
    atomicAdd(reinterpret_cast<float4*>(g_agg + (size_t)d * 128 + lane * 4), msg);

    if (w_out != nullptr && lane == 0) w_out[e] = wgt;
}

// ---------------- launch ----------------
extern "C" void kernel_launch(void* const* d_in, const int* in_sizes, int n_in,
                              void* d_out, int out_size)
{
    const float* nf     = (const float*)d_in[0];
    const float* ef     = (const float*)d_in[1];
    const int*   ei     = (const int*)  d_in[2];
    const float* W_node = (const float*)d_in[3];
    const float* b_node = (const float*)d_in[4];
    const float* W_edge = (const float*)d_in[5];
    const float* b_edge = (const float*)d_in[6];
    const float* W_gnn  = (const float*)d_in[7];
    const float* b_gnn  = (const float*)d_in[8];
    const float* W_top  = (const float*)d_in[9];
    const float* b_top  = (const float*)d_in[10];
    const float* ln_s   = (const float*)d_in[11];
    const float* ln_b   = (const float*)d_in[12];

    float* out       = (float*)d_out;
    float* out_nodes = out;
    float* out_w     = out + (size_t)NN * 128;

    const int* src = ei;
    const int* dst = ei + NE;

    const int SMEM_SZ = 2 * 4 * 128 * 80;   // 81920 B
    cudaFuncSetAttribute(mma_gemm_kernel<128, 0>, cudaFuncAttributeMaxDynamicSharedMemorySize, SMEM_SZ);
    cudaFuncSetAttribute(mma_gemm_kernel<64, 3>,  cudaFuncAttributeMaxDynamicSharedMemorySize, SMEM_SZ);
    cudaFuncSetAttribute(mma_gemm_kernel<256, 2>, cudaFuncAttributeMaxDynamicSharedMemorySize, SMEM_SZ);

    __nv_bfloat16 *wthn = nullptr, *wtln = nullptr, *wthe = nullptr, *wtle = nullptr;
    __nv_bfloat16 *wthg = nullptr, *wtlg = nullptr;
    cudaGetSymbolAddress((void**)&wthn, g_wth_node);
    cudaGetSymbolAddress((void**)&wtln, g_wtl_node);
    cudaGetSymbolAddress((void**)&wthe, g_wth_edge);
    cudaGetSymbolAddress((void**)&wtle, g_wtl_edge);
    cudaGetSymbolAddress((void**)&wthg, g_wth_gnn);
    cudaGetSymbolAddress((void**)&wtlg, g_wtl_gnn);
    float* nodeh = nullptr; float* aggep = nullptr;
    float* efsum = nullptr; float* indeg = nullptr; float* aggp = nullptr;
    cudaGetSymbolAddress((void**)&nodeh, g_node_h);
    cudaGetSymbolAddress((void**)&aggep, g_agg_e);
    cudaGetSymbolAddress((void**)&efsum, g_ef_sum);
    cudaGetSymbolAddress((void**)&indeg, g_indeg);
    cudaGetSymbolAddress((void**)&aggp, g_agg);

    // fused prologue (zeros + transposes + ve)
    prep_kernel<<<(PREP_TOTAL + 255) / 256, 256>>>(W_node, W_edge, W_gnn, b_edge, W_top);

    // edge feature sum + edot (replaces the 200000-row edge GEMM)
    edge_sum_kernel<<<(NE * 16 + 255) / 256, 256>>>(ef, dst);

    // node embed (+ a,b dots)
    mma_gemm_kernel<128, 0><<<(NN + 127) / 128, 256, SMEM_SZ>>>(
        nf, wthn, wtln, b_node, NN, W_top, nullptr, nullptr, nullptr, 0);
    // agg_e = ef_sum @ W_edge + indeg * b_edge  (tiny GEMM)
    mma_gemm_kernel<64, 3><<<(NN + 127) / 128, 256, SMEM_SZ>>>(
        efsum, wthe, wtle, b_edge, NN, indeg, nullptr, nullptr, aggep, 0);

    for (int i = 0; i < 3; i++) {
        zero_buf_kernel<<<1024, 256>>>(aggp, NN * 128 / 4);
        edge_kernel<<<(NE * 32 + 255) / 256, 256>>>(
            src, dst, b_top, (i == 2) ? out_w : nullptr);
        mma_gemm_kernel<256, 2><<<(NN + 127) / 128, 256, SMEM_SZ>>>(
            nullptr, wthg + (size_t)i * 128 * 256, wtlg + (size_t)i * 128 * 256,
            b_gnn + i * 128, NN,
            W_top, ln_s + i * 128, ln_b + i * 128,
            (i == 2) ? out_nodes : nodeh, (i < 2) ? 1 : 0);
    }
}